// round 13
// baseline (speedup 1.0000x reference)
#include <cuda_runtime.h>
#include <math.h>
#include <stdint.h>

#define BATCH 32768
#define SDIM 512
#define HID 256
#define ACT 8
#define HOR 10

// ---------------- scratch (device globals; no allocation) ----------------
__device__ float g_init[BATCH * 2 * HID];
__device__ float g_h0b[BATCH * HID];
__device__ float g_h1b[BATCH * HID];
__device__ float g_a0[BATCH * ACT];
__device__ float g_a1[BATCH * ACT];

// packed tf32 fragment-ordered weights
__device__ uint32_t g_W1p[256 * 1024];
__device__ uint32_t g_W2p[256 * 256];
__device__ uint32_t g_Winitp[512 * 256];
__device__ uint32_t g_Wih1p[768 * 256];
__device__ uint32_t g_Whh1p[768 * 256];
__device__ uint32_t g_Whh0p[768 * 256];
__device__ uint32_t g_Wih0p[768 * 8];

// ---------------- helpers ----------------
__device__ __forceinline__ uint32_t f2tf(float f) {
    uint32_t u;
    asm("cvt.rna.tf32.f32 %0, %1;" : "=r"(u) : "f"(f));
    return u;
}

__device__ __forceinline__ void mma8(float c[4], const uint32_t a[4],
                                     uint32_t b0, uint32_t b1) {
    asm volatile(
        "mma.sync.aligned.m16n8k8.row.col.f32.tf32.tf32.f32 "
        "{%0,%1,%2,%3}, {%4,%5,%6,%7}, {%8,%9}, {%0,%1,%2,%3};"
        : "+f"(c[0]), "+f"(c[1]), "+f"(c[2]), "+f"(c[3])
        : "r"(a[0]), "r"(a[1]), "r"(a[2]), "r"(a[3]), "r"(b0), "r"(b1));
}

__device__ __forceinline__ float sigm(float x) {
    return 1.0f / (1.0f + expf(-x));
}

__device__ __forceinline__ uint4 ldfrag(const uint32_t* __restrict__ Wp,
                                        int nb, int kb, int KB, int lane) {
    return *(const uint4*)&Wp[((nb * KB + kb) * 32 + lane) * 4];
}

__device__ __forceinline__ void cp_async16(uint32_t smem_addr, const void* gptr) {
    asm volatile("cp.async.cg.shared.global [%0], [%1], 16;"
                 :: "r"(smem_addr), "l"(gptr) : "memory");
}
#define CP_COMMIT() asm volatile("cp.async.commit_group;" ::: "memory")
#define CP_WAIT1()  asm volatile("cp.async.wait_group 1;" ::: "memory")

__device__ __forceinline__ uint32_t smem_u32(const void* p) {
    return (uint32_t)__cvta_generic_to_shared(p);
}

// ---------------- fused pack + zero kernel ----------------
__device__ __forceinline__ void pack_one(const float* __restrict__ W,
                                         uint32_t* __restrict__ Wp, int K, int i) {
    int KB = K >> 4;
    int q = i & 3;
    int lane = (i >> 2) & 31;
    int t = i >> 7;
    int kb = t % KB, nb = t / KB;
    int col = nb * 8 + (lane >> 2);
    int k = kb * 16 + q * 4 + (lane & 3);
    Wp[i] = f2tf(W[col * K + k]);
}

#define PK_S0 262144
#define PK_S1 (PK_S0 + 65536)
#define PK_S2 (PK_S1 + 131072)
#define PK_S3 (PK_S2 + 196608)
#define PK_S4 (PK_S3 + 196608)
#define PK_S5 (PK_S4 + 196608)
#define PK_S6 (PK_S5 + 6144)
#define PK_TOT (PK_S6 + 262144)

__global__ void k_pack_all(const float* __restrict__ W1, const float* __restrict__ W2,
                           const float* __restrict__ Winit, const float* __restrict__ Wih1,
                           const float* __restrict__ Whh1, const float* __restrict__ Whh0,
                           const float* __restrict__ Wih0, float* __restrict__ a0)
{
    int i = blockIdx.x * blockDim.x + threadIdx.x;
    if (i >= PK_TOT) return;
    if (i < PK_S0)      { pack_one(W1,    g_W1p,    1024, i); }
    else if (i < PK_S1) { pack_one(W2,    g_W2p,    256,  i - PK_S0); }
    else if (i < PK_S2) { pack_one(Winit, g_Winitp, 256,  i - PK_S1); }
    else if (i < PK_S3) { pack_one(Wih1,  g_Wih1p,  256,  i - PK_S2); }
    else if (i < PK_S4) { pack_one(Whh1,  g_Whh1p,  256,  i - PK_S3); }
    else if (i < PK_S5) { pack_one(Whh0,  g_Whh0p,  256,  i - PK_S4); }
    else if (i < PK_S6) {
        int j = i - PK_S5;
        int q = j & 1;
        int lane = (j >> 1) & 31;
        int nb = j >> 6;
        int col = nb * 8 + (lane >> 2);
        int k = q * 4 + (lane & 3);
        g_Wih0p[j] = f2tf(Wih0[col * 8 + k]);
    } else {
        a0[i - PK_S6] = 0.0f;
    }
}

// ---------------- fused MLP (exact R12) ----------------
__global__ __launch_bounds__(256) void k_mlp(
    const float* __restrict__ s0, const float* __restrict__ s1,
    const uint32_t* __restrict__ W1p, const float* __restrict__ b1,
    const float* __restrict__ gam, const float* __restrict__ bet,
    const uint32_t* __restrict__ W2p, const float* __restrict__ b2,
    const uint32_t* __restrict__ Winitp, const float* __restrict__ binit,
    float* __restrict__ initout)
{
    extern __shared__ __align__(16) uint32_t DSM[];
    uint32_t* SB = DSM;
    uint32_t* H1 = DSM + 8448;

    const int tid  = threadIdx.x;
    const int rowBase = blockIdx.x * 32;
    const int warp = tid >> 5, lane = tid & 31;
    const int wm = warp >> 2, wn = warp & 3;
    const int g  = lane >> 2, t4 = lane & 3;

    float acc[8][4];
#pragma unroll
    for (int i = 0; i < 8; i++)
#pragma unroll
        for (int j = 0; j < 4; j++) acc[i][j] = 0.0f;

    for (int k0 = 0; k0 < 1024; k0 += 16) {
        if (tid < 128) {
            int r = tid >> 2, lk = (tid & 3) * 4;
            int k = k0 + lk;
            float4 v;
            if (k < 512) v = *(const float4*)&s0[(rowBase + r) * 512 + k];
            else         v = *(const float4*)&s1[(rowBase + r) * 512 + (k - 512)];
            uint32_t* Xp = &SB[r * 20 + lk];
            Xp[0] = f2tf(v.x); Xp[1] = f2tf(v.y); Xp[2] = f2tf(v.z); Xp[3] = f2tf(v.w);
        }
        __syncthreads();
        uint32_t a[2][4];
#pragma unroll
        for (int ks = 0; ks < 2; ks++) {
            a[ks][0] = SB[(wm * 16 + g) * 20 + ks * 8 + t4];
            a[ks][1] = SB[(wm * 16 + g + 8) * 20 + ks * 8 + t4];
            a[ks][2] = SB[(wm * 16 + g) * 20 + ks * 8 + t4 + 4];
            a[ks][3] = SB[(wm * 16 + g + 8) * 20 + ks * 8 + t4 + 4];
        }
        int kb = k0 >> 4;
#pragma unroll
        for (int nt = 0; nt < 8; nt++) {
            uint4 b = ldfrag(W1p, wn * 8 + nt, kb, 64, lane);
            mma8(acc[nt], a[0], b.x, b.y);
            mma8(acc[nt], a[1], b.z, b.w);
        }
        __syncthreads();
    }

    float* Cs = (float*)SB;
#pragma unroll
    for (int nt = 0; nt < 8; nt++)
#pragma unroll
        for (int rix = 0; rix < 4; rix++) {
            int row = wm * 16 + g + 8 * (rix >> 1);
            int col = wn * 64 + nt * 8 + t4 * 2 + (rix & 1);
            Cs[row * 264 + col] = acc[nt][rix];
        }
    __syncthreads();

    for (int rr = 0; rr < 4; rr++) {
        int row = warp * 4 + rr;
        float v[8];
        float sum = 0.0f, sq = 0.0f;
#pragma unroll
        for (int i = 0; i < 8; i++) {
            int c = lane + 32 * i;
            v[i] = Cs[row * 264 + c] + b1[c];
            sum += v[i];
            sq  += v[i] * v[i];
        }
#pragma unroll
        for (int o = 16; o; o >>= 1) {
            sum += __shfl_xor_sync(0xffffffffu, sum, o);
            sq  += __shfl_xor_sync(0xffffffffu, sq, o);
        }
        float mean = sum * (1.0f / 256.0f);
        float var  = sq * (1.0f / 256.0f) - mean * mean;
        float rstd = rsqrtf(var + 1e-5f);
#pragma unroll
        for (int i = 0; i < 8; i++) {
            int c = lane + 32 * i;
            float o = (v[i] - mean) * rstd * gam[c] + bet[c];
            H1[row * 260 + c] = f2tf(fmaxf(o, 0.0f));
        }
    }
    __syncthreads();

#pragma unroll
    for (int i = 0; i < 8; i++)
#pragma unroll
        for (int j = 0; j < 4; j++) acc[i][j] = 0.0f;

    for (int kb = 0; kb < 16; kb++) {
        uint32_t a[2][4];
#pragma unroll
        for (int ks = 0; ks < 2; ks++) {
            int kc = kb * 16 + ks * 8;
            a[ks][0] = H1[(wm * 16 + g) * 260 + kc + t4];
            a[ks][1] = H1[(wm * 16 + g + 8) * 260 + kc + t4];
            a[ks][2] = H1[(wm * 16 + g) * 260 + kc + t4 + 4];
            a[ks][3] = H1[(wm * 16 + g + 8) * 260 + kc + t4 + 4];
        }
#pragma unroll
        for (int nt = 0; nt < 8; nt++) {
            uint4 b = ldfrag(W2p, wn * 8 + nt, kb, 16, lane);
            mma8(acc[nt], a[0], b.x, b.y);
            mma8(acc[nt], a[1], b.z, b.w);
        }
    }
#pragma unroll
    for (int nt = 0; nt < 8; nt++)
#pragma unroll
        for (int rix = 0; rix < 4; rix++) {
            int row = wm * 16 + g + 8 * (rix >> 1);
            int col = wn * 64 + nt * 8 + t4 * 2 + (rix & 1);
            SB[row * 260 + col] = f2tf(fmaxf(acc[nt][rix] + b2[col], 0.0f));
        }
    __syncthreads();

    for (int nh = 0; nh < 2; nh++) {
#pragma unroll
        for (int i = 0; i < 8; i++)
#pragma unroll
            for (int j = 0; j < 4; j++) acc[i][j] = 0.0f;

        for (int kb = 0; kb < 16; kb++) {
            uint32_t a[2][4];
#pragma unroll
            for (int ks = 0; ks < 2; ks++) {
                int kc = kb * 16 + ks * 8;
                a[ks][0] = SB[(wm * 16 + g) * 260 + kc + t4];
                a[ks][1] = SB[(wm * 16 + g + 8) * 260 + kc + t4];
                a[ks][2] = SB[(wm * 16 + g) * 260 + kc + t4 + 4];
                a[ks][3] = SB[(wm * 16 + g + 8) * 260 + kc + t4 + 4];
            }
#pragma unroll
            for (int nt = 0; nt < 8; nt++) {
                uint4 b = ldfrag(Winitp, nh * 32 + wn * 8 + nt, kb, 16, lane);
                mma8(acc[nt], a[0], b.x, b.y);
                mma8(acc[nt], a[1], b.z, b.w);
            }
        }
#pragma unroll
        for (int nt = 0; nt < 8; nt++)
#pragma unroll
            for (int rix = 0; rix < 4; rix++) {
                int row = wm * 16 + g + 8 * (rix >> 1);
                int col = wn * 64 + nt * 8 + t4 * 2 + (rix & 1);
                initout[(rowBase + row) * 512 + nh * 256 + col] =
                    acc[nt][rix] + binit[nh * 256 + col];
            }
    }
}

// ---------------- GRU cell 1: R4 math + cp.async double-buffered weights ----------------
// dyn smem: Xs[1280] | Hs[1280] | Wsm[2][48][128]  (frag f = (wn*2+nt)*6+pg)
__global__ __launch_bounds__(256) void k_gru1_mma(
    const float* __restrict__ x_in, const float* __restrict__ h_in,
    const uint32_t* __restrict__ Wihp, const uint32_t* __restrict__ Whhp,
    const float* __restrict__ bih, const float* __restrict__ bhh,
    float* __restrict__ h_out)
{
    extern __shared__ __align__(16) uint32_t SM1[];
    uint32_t* Xs  = SM1;           // 64*20
    uint32_t* Hs  = SM1 + 1280;    // 64*20
    uint32_t* Wsm = SM1 + 2560;    // 2*6144

    const int tid = threadIdx.x;
    const int m0 = blockIdx.y * 64, c0b = blockIdx.x * 64;
    const int warp = tid >> 5, lane = tid & 31;
    const int wm = warp >> 2, wn = warp & 3;
    const int g = lane >> 2, t4 = lane & 3;
    const int lr = tid >> 2, lk = (tid & 3) * 4;
    const int nb0 = c0b >> 3;
    const uint32_t wsm_u = smem_u32(Wsm);

    float accR[2][2][4], accZ[2][2][4], accIN[2][2][4], accHN[2][2][4];
#pragma unroll
    for (int mf = 0; mf < 2; mf++)
#pragma unroll
        for (int nt = 0; nt < 2; nt++)
#pragma unroll
            for (int j = 0; j < 4; j++) {
                accR[mf][nt][j] = 0.0f; accZ[mf][nt][j] = 0.0f;
                accIN[mf][nt][j] = 0.0f; accHN[mf][nt][j] = 0.0f;
            }

    // weight stage issue: 48 frags x 32 lanes x 16B = 1536 chunks, 6/thread
#define G1_ISSUE(KT, S)                                                          \
    {                                                                            \
        _Pragma("unroll")                                                        \
        for (int i = 0; i < 6; i++) {                                            \
            int c = i * 256 + tid;                                               \
            int l = c & 31, f = c >> 5;                                          \
            int pg = f % 6, wnnt = f / 6;                                        \
            const uint32_t* Wsrc = (pg < 3) ? Wihp : Whhp;                       \
            int nb = (pg % 3) * 32 + nb0 + wnnt;                                 \
            cp_async16(wsm_u + ((S) * 6144 + f * 128 + l * 4) * 4,               \
                       Wsrc + (((nb * 16 + (KT)) * 32 + l) * 4));                \
        }                                                                        \
    }

    G1_ISSUE(0, 0);
    CP_COMMIT();

    for (int kt = 0; kt < 16; kt++) {
        const int cur = kt & 1;
        // stage activations (exact R4 staging)
        {
            float4 xv = *(const float4*)&x_in[(m0 + lr) * 256 + kt * 16 + lk];
            float4 hv = *(const float4*)&h_in[(m0 + lr) * 256 + kt * 16 + lk];
            Xs[lr * 20 + lk + 0] = f2tf(xv.x); Xs[lr * 20 + lk + 1] = f2tf(xv.y);
            Xs[lr * 20 + lk + 2] = f2tf(xv.z); Xs[lr * 20 + lk + 3] = f2tf(xv.w);
            Hs[lr * 20 + lk + 0] = f2tf(hv.x); Hs[lr * 20 + lk + 1] = f2tf(hv.y);
            Hs[lr * 20 + lk + 2] = f2tf(hv.z); Hs[lr * 20 + lk + 3] = f2tf(hv.w);
        }
        if (kt < 15) G1_ISSUE(kt + 1, cur ^ 1);
        CP_COMMIT();
        CP_WAIT1();
        __syncthreads();

        uint32_t ax[2][2][4], ah[2][2][4];
#pragma unroll
        for (int mf = 0; mf < 2; mf++) {
            int rb = wm * 32 + mf * 16 + g;
#pragma unroll
            for (int ks = 0; ks < 2; ks++) {
                ax[mf][ks][0] = Xs[rb * 20 + ks * 8 + t4];
                ax[mf][ks][1] = Xs[(rb + 8) * 20 + ks * 8 + t4];
                ax[mf][ks][2] = Xs[rb * 20 + ks * 8 + t4 + 4];
                ax[mf][ks][3] = Xs[(rb + 8) * 20 + ks * 8 + t4 + 4];
                ah[mf][ks][0] = Hs[rb * 20 + ks * 8 + t4];
                ah[mf][ks][1] = Hs[(rb + 8) * 20 + ks * 8 + t4];
                ah[mf][ks][2] = Hs[rb * 20 + ks * 8 + t4 + 4];
                ah[mf][ks][3] = Hs[(rb + 8) * 20 + ks * 8 + t4 + 4];
            }
        }

#pragma unroll
        for (int nt = 0; nt < 2; nt++) {
            const uint32_t* Wc = &Wsm[cur * 6144 + ((wn * 2 + nt) * 6) * 128 + lane * 4];
            uint4 b_ir = *(const uint4*)&Wc[0 * 128];
            uint4 b_iz = *(const uint4*)&Wc[1 * 128];
            uint4 b_in = *(const uint4*)&Wc[2 * 128];
            uint4 b_hr = *(const uint4*)&Wc[3 * 128];
            uint4 b_hz = *(const uint4*)&Wc[4 * 128];
            uint4 b_hn = *(const uint4*)&Wc[5 * 128];
#pragma unroll
            for (int mf = 0; mf < 2; mf++) {
                mma8(accR[mf][nt],  ax[mf][0], b_ir.x, b_ir.y);
                mma8(accR[mf][nt],  ax[mf][1], b_ir.z, b_ir.w);
                mma8(accR[mf][nt],  ah[mf][0], b_hr.x, b_hr.y);
                mma8(accR[mf][nt],  ah[mf][1], b_hr.z, b_hr.w);
                mma8(accZ[mf][nt],  ax[mf][0], b_iz.x, b_iz.y);
                mma8(accZ[mf][nt],  ax[mf][1], b_iz.z, b_iz.w);
                mma8(accZ[mf][nt],  ah[mf][0], b_hz.x, b_hz.y);
                mma8(accZ[mf][nt],  ah[mf][1], b_hz.z, b_hz.w);
                mma8(accIN[mf][nt], ax[mf][0], b_in.x, b_in.y);
                mma8(accIN[mf][nt], ax[mf][1], b_in.z, b_in.w);
                mma8(accHN[mf][nt], ah[mf][0], b_hn.x, b_hn.y);
                mma8(accHN[mf][nt], ah[mf][1], b_hn.z, b_hn.w);
            }
        }
        __syncthreads();
    }

#pragma unroll
    for (int mf = 0; mf < 2; mf++)
#pragma unroll
        for (int nt = 0; nt < 2; nt++)
#pragma unroll
            for (int rix = 0; rix < 4; rix++) {
                int row = m0 + wm * 32 + mf * 16 + g + 8 * (rix >> 1);
                int col = c0b + wn * 16 + nt * 8 + t4 * 2 + (rix & 1);
                float r = sigm(accR[mf][nt][rix] + bih[col] + bhh[col]);
                float z = sigm(accZ[mf][nt][rix] + bih[col + 256] + bhh[col + 256]);
                float n = tanhf(accIN[mf][nt][rix] + bih[col + 512] +
                                r * (accHN[mf][nt][rix] + bhh[col + 512]));
                float hold = h_in[row * 256 + col];
                h_out[row * 256 + col] = (1.0f - z) * n + z * hold;
            }
#undef G1_ISSUE
}

// ---------------- GRU cell 0: R4 math + cp.async weights (h path) ----------------
__global__ __launch_bounds__(256) void k_gru0_mma(
    const float* __restrict__ a_in, const float* __restrict__ h_in,
    const uint32_t* __restrict__ Wih0p, const uint32_t* __restrict__ Whhp,
    const float* __restrict__ bih, const float* __restrict__ bhh,
    float* __restrict__ h_out)
{
    __shared__ __align__(16) uint32_t Hs[64 * 20];
    __shared__ __align__(16) uint32_t As[64 * 12];
    __shared__ __align__(16) uint32_t Wsm[2 * 24 * 128];

    const int tid = threadIdx.x;
    const int m0 = blockIdx.y * 64, c0b = blockIdx.x * 64;
    const int warp = tid >> 5, lane = tid & 31;
    const int wm = warp >> 2, wn = warp & 3;
    const int g = lane >> 2, t4 = lane & 3;
    const int lr = tid >> 2, lk = (tid & 3) * 4;
    const int nb0 = c0b >> 3;
    const uint32_t wsm_u = smem_u32(Wsm);

    float accR[2][2][4], accZ[2][2][4], accIN[2][2][4], accHN[2][2][4];
#pragma unroll
    for (int mf = 0; mf < 2; mf++)
#pragma unroll
        for (int nt = 0; nt < 2; nt++)
#pragma unroll
            for (int j = 0; j < 4; j++) {
                accR[mf][nt][j] = 0.0f; accZ[mf][nt][j] = 0.0f;
                accIN[mf][nt][j] = 0.0f; accHN[mf][nt][j] = 0.0f;
            }

    // 24 frags x 32 lanes = 768 chunks, 3/thread
#define G0_ISSUE(KT, S)                                                          \
    {                                                                            \
        _Pragma("unroll")                                                        \
        for (int i = 0; i < 3; i++) {                                            \
            int c = i * 256 + tid;                                               \
            int l = c & 31, f = c >> 5;                                          \
            int gg = f % 3, wnnt = f / 3;                                        \
            int nb = gg * 32 + nb0 + wnnt;                                       \
            cp_async16(wsm_u + ((S) * 3072 + f * 128 + l * 4) * 4,               \
                       Whhp + (((nb * 16 + (KT)) * 32 + l) * 4));                \
        }                                                                        \
    }

    G0_ISSUE(0, 0);
    CP_COMMIT();

    // x path (K=8) staged + computed while stage 0 flies
    {
        int r = tid >> 2, k2 = (tid & 3) * 2;
        float2 av = *(const float2*)&a_in[(m0 + r) * 8 + k2];
        As[r * 12 + k2] = f2tf(av.x); As[r * 12 + k2 + 1] = f2tf(av.y);
    }
    __syncthreads();
    {
        uint32_t a[2][4];
#pragma unroll
        for (int mf = 0; mf < 2; mf++) {
            int rb = wm * 32 + mf * 16 + g;
            a[mf][0] = As[rb * 12 + t4];
            a[mf][1] = As[(rb + 8) * 12 + t4];
            a[mf][2] = As[rb * 12 + t4 + 4];
            a[mf][3] = As[(rb + 8) * 12 + t4 + 4];
        }
#pragma unroll
        for (int nt = 0; nt < 2; nt++) {
            int nbB = nb0 + wn * 2 + nt;
            uint2 b_ir = *(const uint2*)&Wih0p[((     nbB) * 32 + lane) * 2];
            uint2 b_iz = *(const uint2*)&Wih0p[((32 + nbB) * 32 + lane) * 2];
            uint2 b_in = *(const uint2*)&Wih0p[((64 + nbB) * 32 + lane) * 2];
#pragma unroll
            for (int mf = 0; mf < 2; mf++) {
                mma8(accR[mf][nt],  a[mf], b_ir.x, b_ir.y);
                mma8(accZ[mf][nt],  a[mf], b_iz.x, b_iz.y);
                mma8(accIN[mf][nt], a[mf], b_in.x, b_in.y);
            }
        }
    }
    __syncthreads();

    // h path (K=256)
    for (int kt = 0; kt < 16; kt++) {
        const int cur = kt & 1;
        {
            float4 hv = *(const float4*)&h_in[(m0 + lr) * 256 + kt * 16 + lk];
            Hs[lr * 20 + lk + 0] = f2tf(hv.x); Hs[lr * 20 + lk + 1] = f2tf(hv.y);
            Hs[lr * 20 + lk + 2] = f2tf(hv.z); Hs[lr * 20 + lk + 3] = f2tf(hv.w);
        }
        if (kt < 15) G0_ISSUE(kt + 1, cur ^ 1);
        CP_COMMIT();
        CP_WAIT1();
        __syncthreads();

        uint32_t ah[2][2][4];
#pragma unroll
        for (int mf = 0; mf < 2; mf++) {
            int rb = wm * 32 + mf * 16 + g;
#pragma unroll
            for (int ks = 0; ks < 2; ks++) {
                ah[mf][ks][0] = Hs[rb * 20 + ks * 8 + t4];
                ah[mf][ks][1] = Hs[(rb + 8) * 20 + ks * 8 + t4];
                ah[mf][ks][2] = Hs[rb * 20 + ks * 8 + t4 + 4];
                ah[mf][ks][3] = Hs[(rb + 8) * 20 + ks * 8 + t4 + 4];
            }
        }

#pragma unroll
        for (int nt = 0; nt < 2; nt++) {
            const uint32_t* Wc = &Wsm[cur * 3072 + ((wn * 2 + nt) * 3) * 128 + lane * 4];
            uint4 b_hr = *(const uint4*)&Wc[0 * 128];
            uint4 b_hz = *(const uint4*)&Wc[1 * 128];
            uint4 b_hn = *(const uint4*)&Wc[2 * 128];
#pragma unroll
            for (int mf = 0; mf < 2; mf++) {
                mma8(accR[mf][nt],  ah[mf][0], b_hr.x, b_hr.y);
                mma8(accR[mf][nt],  ah[mf][1], b_hr.z, b_hr.w);
                mma8(accZ[mf][nt],  ah[mf][0], b_hz.x, b_hz.y);
                mma8(accZ[mf][nt],  ah[mf][1], b_hz.z, b_hz.w);
                mma8(accHN[mf][nt], ah[mf][0], b_hn.x, b_hn.y);
                mma8(accHN[mf][nt], ah[mf][1], b_hn.z, b_hn.w);
            }
        }
        __syncthreads();
    }

#pragma unroll
    for (int mf = 0; mf < 2; mf++)
#pragma unroll
        for (int nt = 0; nt < 2; nt++)
#pragma unroll
            for (int rix = 0; rix < 4; rix++) {
                int row = m0 + wm * 32 + mf * 16 + g + 8 * (rix >> 1);
                int col = c0b + wn * 16 + nt * 8 + t4 * 2 + (rix & 1);
                float r = sigm(accR[mf][nt][rix] + bih[col] + bhh[col]);
                float z = sigm(accZ[mf][nt][rix] + bih[col + 256] + bhh[col + 256]);
                float n = tanhf(accIN[mf][nt][rix] + bih[col + 512] +
                                r * (accHN[mf][nt][rix] + bhh[col + 512]));
                float hold = h_in[row * 256 + col];
                h_out[row * 256 + col] = (1.0f - z) * n + z * hold;
            }
#undef G0_ISSUE
}

// ---------------- logits + softmax ----------------
__global__ __launch_bounds__(256) void k_logits(
    const float* __restrict__ h, const float* __restrict__ Wa,
    const float* __restrict__ ba, float* __restrict__ out,
    float* __restrict__ a_next, int t)
{
    __shared__ float hs[32][257];
    __shared__ float Was[8][257];

    const int tid = threadIdx.x;
    const int rb0 = blockIdx.x * 32;

#pragma unroll
    for (int i = 0; i < 8; i++) {
        int idx = i * 256 + tid;
        int j = idx >> 8, k = idx & 255;
        Was[j][k] = Wa[j * 256 + k];
    }
#pragma unroll
    for (int i = 0; i < 32; i++) {
        int idx = i * 256 + tid;
        int r = idx >> 8, k = idx & 255;
        hs[r][k] = h[(rb0 + r) * 256 + k];
    }
    __syncthreads();

    const int r = tid >> 3, j = tid & 7;
    float s0 = 0.0f, s1 = 0.0f, s2 = 0.0f, s3 = 0.0f;
#pragma unroll 8
    for (int k = 0; k < 256; k += 4) {
        s0 += hs[r][k + 0] * Was[j][k + 0];
        s1 += hs[r][k + 1] * Was[j][k + 1];
        s2 += hs[r][k + 2] * Was[j][k + 2];
        s3 += hs[r][k + 3] * Was[j][k + 3];
    }
    float acc = (s0 + s1) + (s2 + s3) + ba[j];

    out[(rb0 + r) * (HOR * ACT) + t * ACT + j] = acc;

    float m = acc;
#pragma unroll
    for (int o = 4; o; o >>= 1) m = fmaxf(m, __shfl_xor_sync(0xffffffffu, m, o));
    float e = expf(acc - m);
    float s = e;
#pragma unroll
    for (int o = 4; o; o >>= 1) s += __shfl_xor_sync(0xffffffffu, s, o);
    a_next[(rb0 + r) * ACT + j] = e / s;
}

// ---------------- host ----------------
extern "C" void kernel_launch(void* const* d_in, const int* in_sizes, int n_in,
                              void* d_out, int out_size)
{
    const float* s0    = (const float*)d_in[0];
    const float* s1    = (const float*)d_in[1];
    const float* W1    = (const float*)d_in[3];
    const float* b1    = (const float*)d_in[4];
    const float* lng   = (const float*)d_in[5];
    const float* lnb   = (const float*)d_in[6];
    const float* W2    = (const float*)d_in[7];
    const float* b2    = (const float*)d_in[8];
    const float* Wih0  = (const float*)d_in[9];
    const float* Whh0  = (const float*)d_in[10];
    const float* bih0  = (const float*)d_in[11];
    const float* bhh0  = (const float*)d_in[12];
    const float* Wih1  = (const float*)d_in[13];
    const float* Whh1  = (const float*)d_in[14];
    const float* bih1  = (const float*)d_in[15];
    const float* bhh1  = (const float*)d_in[16];
    const float* Wa    = (const float*)d_in[17];
    const float* ba    = (const float*)d_in[18];
    const float* Winit = (const float*)d_in[19];
    const float* binit = (const float*)d_in[20];
    float* out = (float*)d_out;

    float *initbuf, *h0b, *h1b, *a0, *a1;
    uint32_t *W1p, *W2p, *Winitp, *Wih1p, *Whh1p, *Whh0p, *Wih0p;
    cudaGetSymbolAddress((void**)&initbuf, g_init);
    cudaGetSymbolAddress((void**)&h0b, g_h0b);
    cudaGetSymbolAddress((void**)&h1b, g_h1b);
    cudaGetSymbolAddress((void**)&a0, g_a0);
    cudaGetSymbolAddress((void**)&a1, g_a1);
    cudaGetSymbolAddress((void**)&W1p, g_W1p);
    cudaGetSymbolAddress((void**)&W2p, g_W2p);
    cudaGetSymbolAddress((void**)&Winitp, g_Winitp);
    cudaGetSymbolAddress((void**)&Wih1p, g_Wih1p);
    cudaGetSymbolAddress((void**)&Whh1p, g_Whh1p);
    cudaGetSymbolAddress((void**)&Whh0p, g_Whh0p);
    cudaGetSymbolAddress((void**)&Wih0p, g_Wih0p);

    static int attrs_set = 0;
    const int MLP_SMEM = (8448 + 8320) * 4;
    const int G1_SMEM  = (2560 + 12288) * 4;   // 59392 B
    if (!attrs_set) {
        cudaFuncSetAttribute(k_mlp, cudaFuncAttributeMaxDynamicSharedMemorySize, MLP_SMEM);
        cudaFuncSetAttribute(k_gru1_mma, cudaFuncAttributeMaxDynamicSharedMemorySize, G1_SMEM);
        attrs_set = 1;
    }

    // launch 1: fused pack + a0 zero
    k_pack_all<<<(PK_TOT + 255) / 256, 256>>>(W1, W2, Winit, Wih1, Whh1, Whh0, Wih0, a0);

    // launch 2: fused prologue MLP
    k_mlp<<<BATCH / 32, 256, MLP_SMEM>>>(s0, s1, W1p, b1, lng, lnb,
                                         W2p, b2, Winitp, binit, initbuf);

    float* h0bufs[2] = {initbuf, h0b};
    float* h1bufs[2] = {initbuf + BATCH * HID, h1b};
    float* abufs[2]  = {a0, a1};

    // launch 3: gru0(t=0); launch 4: gru1(t=0)  <- profiled slot
    for (int t = 0; t < HOR; t++) {
        int cur = t & 1, nxt = 1 - cur;
        k_gru0_mma<<<dim3(4, BATCH / 64), 256>>>(abufs[cur], h0bufs[cur],
                                                 Wih0p, Whh0p, bih0, bhh0, h0bufs[nxt]);
        k_gru1_mma<<<dim3(4, BATCH / 64), 256, G1_SMEM>>>(h0bufs[nxt], h1bufs[cur],
                                                          Wih1p, Whh1p, bih1, bhh1, h1bufs[nxt]);
        k_logits<<<BATCH / 32, 256>>>(h1bufs[nxt], Wa, ba, out, abufs[nxt], t);
    }
}

// round 15
// speedup vs baseline: 1.2758x; 1.2758x over previous
#include <cuda_runtime.h>
#include <math.h>
#include <stdint.h>

#define BATCH 32768
#define SDIM 512
#define HID 256
#define ACT 8
#define HOR 10

// ---------------- scratch (device globals; no allocation) ----------------
__device__ float g_init[BATCH * 2 * HID];
__device__ float g_h0b[BATCH * HID];
__device__ float g_h1b[BATCH * HID];
__device__ float g_a0[BATCH * ACT];
__device__ float g_a1[BATCH * ACT];

// packed tf32 fragment-ordered weights
__device__ uint32_t g_W1p[256 * 1024];
__device__ uint32_t g_W2p[256 * 256];
__device__ uint32_t g_Winitp[512 * 256];
__device__ uint32_t g_Wih1p[768 * 256];
__device__ uint32_t g_Whh1p[768 * 256];
__device__ uint32_t g_Whh0p[768 * 256];
__device__ uint32_t g_Wih0p[768 * 8];

// ---------------- helpers ----------------
__device__ __forceinline__ uint32_t f2tf(float f) {
    uint32_t u;
    asm("cvt.rna.tf32.f32 %0, %1;" : "=r"(u) : "f"(f));
    return u;
}

__device__ __forceinline__ void mma8(float c[4], const uint32_t a[4],
                                     uint32_t b0, uint32_t b1) {
    asm volatile(
        "mma.sync.aligned.m16n8k8.row.col.f32.tf32.tf32.f32 "
        "{%0,%1,%2,%3}, {%4,%5,%6,%7}, {%8,%9}, {%0,%1,%2,%3};"
        : "+f"(c[0]), "+f"(c[1]), "+f"(c[2]), "+f"(c[3])
        : "r"(a[0]), "r"(a[1]), "r"(a[2]), "r"(a[3]), "r"(b0), "r"(b1));
}

__device__ __forceinline__ float sigm(float x) {
    return 1.0f / (1.0f + expf(-x));
}

// fragment load: Wp layout [nb][kb][lane][4]
__device__ __forceinline__ uint4 ldfrag(const uint32_t* __restrict__ Wp,
                                        int nb, int kb, int KB, int lane) {
    return *(const uint4*)&Wp[((nb * KB + kb) * 32 + lane) * 4];
}

// ---------------- fused pack + zero kernel ----------------
__device__ __forceinline__ void pack_one(const float* __restrict__ W,
                                         uint32_t* __restrict__ Wp, int K, int i) {
    int KB = K >> 4;
    int q = i & 3;
    int lane = (i >> 2) & 31;
    int t = i >> 7;
    int kb = t % KB, nb = t / KB;
    int col = nb * 8 + (lane >> 2);
    int k = kb * 16 + q * 4 + (lane & 3);
    Wp[i] = f2tf(W[col * K + k]);
}

#define PK_S0 262144
#define PK_S1 (PK_S0 + 65536)
#define PK_S2 (PK_S1 + 131072)
#define PK_S3 (PK_S2 + 196608)
#define PK_S4 (PK_S3 + 196608)
#define PK_S5 (PK_S4 + 196608)
#define PK_S6 (PK_S5 + 6144)
#define PK_TOT (PK_S6 + 262144)

__global__ void k_pack_all(const float* __restrict__ W1, const float* __restrict__ W2,
                           const float* __restrict__ Winit, const float* __restrict__ Wih1,
                           const float* __restrict__ Whh1, const float* __restrict__ Whh0,
                           const float* __restrict__ Wih0, float* __restrict__ a0)
{
    int i = blockIdx.x * blockDim.x + threadIdx.x;
    if (i >= PK_TOT) return;
    if (i < PK_S0)      { pack_one(W1,    g_W1p,    1024, i); }
    else if (i < PK_S1) { pack_one(W2,    g_W2p,    256,  i - PK_S0); }
    else if (i < PK_S2) { pack_one(Winit, g_Winitp, 256,  i - PK_S1); }
    else if (i < PK_S3) { pack_one(Wih1,  g_Wih1p,  256,  i - PK_S2); }
    else if (i < PK_S4) { pack_one(Whh1,  g_Whh1p,  256,  i - PK_S3); }
    else if (i < PK_S5) { pack_one(Whh0,  g_Whh0p,  256,  i - PK_S4); }
    else if (i < PK_S6) {
        int j = i - PK_S5;
        int q = j & 1;
        int lane = (j >> 1) & 31;
        int nb = j >> 6;
        int col = nb * 8 + (lane >> 2);
        int k = q * 4 + (lane & 3);
        g_Wih0p[j] = f2tf(Wih0[col * 8 + k]);
    } else {
        a0[i - PK_S6] = 0.0f;
    }
}

// ---------------- fused MLP (exact R12) ----------------
__global__ __launch_bounds__(256) void k_mlp(
    const float* __restrict__ s0, const float* __restrict__ s1,
    const uint32_t* __restrict__ W1p, const float* __restrict__ b1,
    const float* __restrict__ gam, const float* __restrict__ bet,
    const uint32_t* __restrict__ W2p, const float* __restrict__ b2,
    const uint32_t* __restrict__ Winitp, const float* __restrict__ binit,
    float* __restrict__ initout)
{
    extern __shared__ __align__(16) uint32_t DSM[];
    uint32_t* SB = DSM;
    uint32_t* H1 = DSM + 8448;

    const int tid  = threadIdx.x;
    const int rowBase = blockIdx.x * 32;
    const int warp = tid >> 5, lane = tid & 31;
    const int wm = warp >> 2, wn = warp & 3;
    const int g  = lane >> 2, t4 = lane & 3;

    float acc[8][4];
#pragma unroll
    for (int i = 0; i < 8; i++)
#pragma unroll
        for (int j = 0; j < 4; j++) acc[i][j] = 0.0f;

    for (int k0 = 0; k0 < 1024; k0 += 16) {
        if (tid < 128) {
            int r = tid >> 2, lk = (tid & 3) * 4;
            int k = k0 + lk;
            float4 v;
            if (k < 512) v = *(const float4*)&s0[(rowBase + r) * 512 + k];
            else         v = *(const float4*)&s1[(rowBase + r) * 512 + (k - 512)];
            uint32_t* Xp = &SB[r * 20 + lk];
            Xp[0] = f2tf(v.x); Xp[1] = f2tf(v.y); Xp[2] = f2tf(v.z); Xp[3] = f2tf(v.w);
        }
        __syncthreads();
        uint32_t a[2][4];
#pragma unroll
        for (int ks = 0; ks < 2; ks++) {
            a[ks][0] = SB[(wm * 16 + g) * 20 + ks * 8 + t4];
            a[ks][1] = SB[(wm * 16 + g + 8) * 20 + ks * 8 + t4];
            a[ks][2] = SB[(wm * 16 + g) * 20 + ks * 8 + t4 + 4];
            a[ks][3] = SB[(wm * 16 + g + 8) * 20 + ks * 8 + t4 + 4];
        }
        int kb = k0 >> 4;
#pragma unroll
        for (int nt = 0; nt < 8; nt++) {
            uint4 b = ldfrag(W1p, wn * 8 + nt, kb, 64, lane);
            mma8(acc[nt], a[0], b.x, b.y);
            mma8(acc[nt], a[1], b.z, b.w);
        }
        __syncthreads();
    }

    float* Cs = (float*)SB;
#pragma unroll
    for (int nt = 0; nt < 8; nt++)
#pragma unroll
        for (int rix = 0; rix < 4; rix++) {
            int row = wm * 16 + g + 8 * (rix >> 1);
            int col = wn * 64 + nt * 8 + t4 * 2 + (rix & 1);
            Cs[row * 264 + col] = acc[nt][rix];
        }
    __syncthreads();

    for (int rr = 0; rr < 4; rr++) {
        int row = warp * 4 + rr;
        float v[8];
        float sum = 0.0f, sq = 0.0f;
#pragma unroll
        for (int i = 0; i < 8; i++) {
            int c = lane + 32 * i;
            v[i] = Cs[row * 264 + c] + b1[c];
            sum += v[i];
            sq  += v[i] * v[i];
        }
#pragma unroll
        for (int o = 16; o; o >>= 1) {
            sum += __shfl_xor_sync(0xffffffffu, sum, o);
            sq  += __shfl_xor_sync(0xffffffffu, sq, o);
        }
        float mean = sum * (1.0f / 256.0f);
        float var  = sq * (1.0f / 256.0f) - mean * mean;
        float rstd = rsqrtf(var + 1e-5f);
#pragma unroll
        for (int i = 0; i < 8; i++) {
            int c = lane + 32 * i;
            float o = (v[i] - mean) * rstd * gam[c] + bet[c];
            H1[row * 260 + c] = f2tf(fmaxf(o, 0.0f));
        }
    }
    __syncthreads();

#pragma unroll
    for (int i = 0; i < 8; i++)
#pragma unroll
        for (int j = 0; j < 4; j++) acc[i][j] = 0.0f;

    for (int kb = 0; kb < 16; kb++) {
        uint32_t a[2][4];
#pragma unroll
        for (int ks = 0; ks < 2; ks++) {
            int kc = kb * 16 + ks * 8;
            a[ks][0] = H1[(wm * 16 + g) * 260 + kc + t4];
            a[ks][1] = H1[(wm * 16 + g + 8) * 260 + kc + t4];
            a[ks][2] = H1[(wm * 16 + g) * 260 + kc + t4 + 4];
            a[ks][3] = H1[(wm * 16 + g + 8) * 260 + kc + t4 + 4];
        }
#pragma unroll
        for (int nt = 0; nt < 8; nt++) {
            uint4 b = ldfrag(W2p, wn * 8 + nt, kb, 16, lane);
            mma8(acc[nt], a[0], b.x, b.y);
            mma8(acc[nt], a[1], b.z, b.w);
        }
    }
#pragma unroll
    for (int nt = 0; nt < 8; nt++)
#pragma unroll
        for (int rix = 0; rix < 4; rix++) {
            int row = wm * 16 + g + 8 * (rix >> 1);
            int col = wn * 64 + nt * 8 + t4 * 2 + (rix & 1);
            SB[row * 260 + col] = f2tf(fmaxf(acc[nt][rix] + b2[col], 0.0f));
        }
    __syncthreads();

    for (int nh = 0; nh < 2; nh++) {
#pragma unroll
        for (int i = 0; i < 8; i++)
#pragma unroll
            for (int j = 0; j < 4; j++) acc[i][j] = 0.0f;

        for (int kb = 0; kb < 16; kb++) {
            uint32_t a[2][4];
#pragma unroll
            for (int ks = 0; ks < 2; ks++) {
                int kc = kb * 16 + ks * 8;
                a[ks][0] = SB[(wm * 16 + g) * 260 + kc + t4];
                a[ks][1] = SB[(wm * 16 + g + 8) * 260 + kc + t4];
                a[ks][2] = SB[(wm * 16 + g) * 260 + kc + t4 + 4];
                a[ks][3] = SB[(wm * 16 + g + 8) * 260 + kc + t4 + 4];
            }
#pragma unroll
            for (int nt = 0; nt < 8; nt++) {
                uint4 b = ldfrag(Winitp, nh * 32 + wn * 8 + nt, kb, 16, lane);
                mma8(acc[nt], a[0], b.x, b.y);
                mma8(acc[nt], a[1], b.z, b.w);
            }
        }
#pragma unroll
        for (int nt = 0; nt < 8; nt++)
#pragma unroll
            for (int rix = 0; rix < 4; rix++) {
                int row = wm * 16 + g + 8 * (rix >> 1);
                int col = wn * 64 + nt * 8 + t4 * 2 + (rix & 1);
                initout[(rowBase + row) * 512 + nh * 256 + col] =
                    acc[nt][rix] + binit[nh * 256 + col];
            }
    }
}

// ---------------- GRU cell 1: BM=64, BN=32; warp 32x8 (mf=2, nt=1); 3 CTAs/SM ----------------
__global__ __launch_bounds__(256, 3) void k_gru1_mma(
    const float* __restrict__ x_in, const float* __restrict__ h_in,
    const uint32_t* __restrict__ Wihp, const uint32_t* __restrict__ Whhp,
    const float* __restrict__ bih, const float* __restrict__ bhh,
    float* __restrict__ h_out)
{
    __shared__ __align__(16) uint32_t Xs[64][20];
    __shared__ __align__(16) uint32_t Hs[64][20];

    const int tid = threadIdx.x;
    const int m0 = blockIdx.y * 64, c0b = blockIdx.x * 32;
    const int warp = tid >> 5, lane = tid & 31;
    const int wm = warp >> 2, wn = warp & 3;
    const int g = lane >> 2, t4 = lane & 3;
    const int lr = tid >> 2, lk = (tid & 3) * 4;

    float accR[2][4], accZ[2][4], accIN[2][4], accHN[2][4];
#pragma unroll
    for (int mf = 0; mf < 2; mf++)
#pragma unroll
        for (int j = 0; j < 4; j++) {
            accR[mf][j] = 0.0f; accZ[mf][j] = 0.0f;
            accIN[mf][j] = 0.0f; accHN[mf][j] = 0.0f;
        }

    const int nbB = (c0b >> 3) + wn;

    for (int k0 = 0; k0 < 256; k0 += 16) {
        float4 xv = *(const float4*)&x_in[(m0 + lr) * 256 + k0 + lk];
        float4 hv = *(const float4*)&h_in[(m0 + lr) * 256 + k0 + lk];
        Xs[lr][lk + 0] = f2tf(xv.x); Xs[lr][lk + 1] = f2tf(xv.y);
        Xs[lr][lk + 2] = f2tf(xv.z); Xs[lr][lk + 3] = f2tf(xv.w);
        Hs[lr][lk + 0] = f2tf(hv.x); Hs[lr][lk + 1] = f2tf(hv.y);
        Hs[lr][lk + 2] = f2tf(hv.z); Hs[lr][lk + 3] = f2tf(hv.w);
        __syncthreads();

        uint32_t ax[2][2][4], ah[2][2][4];
#pragma unroll
        for (int mf = 0; mf < 2; mf++) {
            int rb = wm * 32 + mf * 16 + g;
#pragma unroll
            for (int ks = 0; ks < 2; ks++) {
                ax[mf][ks][0] = Xs[rb][ks * 8 + t4];
                ax[mf][ks][1] = Xs[rb + 8][ks * 8 + t4];
                ax[mf][ks][2] = Xs[rb][ks * 8 + t4 + 4];
                ax[mf][ks][3] = Xs[rb + 8][ks * 8 + t4 + 4];
                ah[mf][ks][0] = Hs[rb][ks * 8 + t4];
                ah[mf][ks][1] = Hs[rb + 8][ks * 8 + t4];
                ah[mf][ks][2] = Hs[rb][ks * 8 + t4 + 4];
                ah[mf][ks][3] = Hs[rb + 8][ks * 8 + t4 + 4];
            }
        }

        int kb = k0 >> 4;
        {
            uint4 b_ir = ldfrag(Wihp,      nbB, kb, 16, lane);
            uint4 b_iz = ldfrag(Wihp, 32 + nbB, kb, 16, lane);
            uint4 b_in = ldfrag(Wihp, 64 + nbB, kb, 16, lane);
            uint4 b_hr = ldfrag(Whhp,      nbB, kb, 16, lane);
            uint4 b_hz = ldfrag(Whhp, 32 + nbB, kb, 16, lane);
            uint4 b_hn = ldfrag(Whhp, 64 + nbB, kb, 16, lane);
#pragma unroll
            for (int mf = 0; mf < 2; mf++) {
                mma8(accR[mf],  ax[mf][0], b_ir.x, b_ir.y);
                mma8(accR[mf],  ax[mf][1], b_ir.z, b_ir.w);
                mma8(accR[mf],  ah[mf][0], b_hr.x, b_hr.y);
                mma8(accR[mf],  ah[mf][1], b_hr.z, b_hr.w);
                mma8(accZ[mf],  ax[mf][0], b_iz.x, b_iz.y);
                mma8(accZ[mf],  ax[mf][1], b_iz.z, b_iz.w);
                mma8(accZ[mf],  ah[mf][0], b_hz.x, b_hz.y);
                mma8(accZ[mf],  ah[mf][1], b_hz.z, b_hz.w);
                mma8(accIN[mf], ax[mf][0], b_in.x, b_in.y);
                mma8(accIN[mf], ax[mf][1], b_in.z, b_in.w);
                mma8(accHN[mf], ah[mf][0], b_hn.x, b_hn.y);
                mma8(accHN[mf], ah[mf][1], b_hn.z, b_hn.w);
            }
        }
        __syncthreads();
    }

#pragma unroll
    for (int mf = 0; mf < 2; mf++)
#pragma unroll
        for (int rix = 0; rix < 4; rix++) {
            int row = m0 + wm * 32 + mf * 16 + g + 8 * (rix >> 1);
            int col = c0b + wn * 8 + t4 * 2 + (rix & 1);
            float r = sigm(accR[mf][rix] + bih[col] + bhh[col]);
            float z = sigm(accZ[mf][rix] + bih[col + 256] + bhh[col + 256]);
            float n = tanhf(accIN[mf][rix] + bih[col + 512] +
                            r * (accHN[mf][rix] + bhh[col + 512]));
            float hold = h_in[row * 256 + col];
            h_out[row * 256 + col] = (1.0f - z) * n + z * hold;
        }
}

// ---------------- GRU cell 0: BM=64, BN=32; warp 32x8 (mf=2, nt=1); 3 CTAs/SM ----------------
__global__ __launch_bounds__(256, 3) void k_gru0_mma(
    const float* __restrict__ a_in, const float* __restrict__ h_in,
    const uint32_t* __restrict__ Wih0p, const uint32_t* __restrict__ Whhp,
    const float* __restrict__ bih, const float* __restrict__ bhh,
    float* __restrict__ h_out)
{
    __shared__ __align__(16) uint32_t Hs[64][20];
    __shared__ __align__(16) uint32_t As[64][12];

    const int tid = threadIdx.x;
    const int m0 = blockIdx.y * 64, c0b = blockIdx.x * 32;
    const int warp = tid >> 5, lane = tid & 31;
    const int wm = warp >> 2, wn = warp & 3;
    const int g = lane >> 2, t4 = lane & 3;
    const int lr = tid >> 2, lk = (tid & 3) * 4;

    float accR[2][4], accZ[2][4], accIN[2][4], accHN[2][4];
#pragma unroll
    for (int mf = 0; mf < 2; mf++)
#pragma unroll
        for (int j = 0; j < 4; j++) {
            accR[mf][j] = 0.0f; accZ[mf][j] = 0.0f;
            accIN[mf][j] = 0.0f; accHN[mf][j] = 0.0f;
        }

    const int nbB = (c0b >> 3) + wn;

    // x path (K=8)
    {
        int r = tid >> 2, k2 = (tid & 3) * 2;
        float2 av = *(const float2*)&a_in[(m0 + r) * 8 + k2];
        As[r][k2] = f2tf(av.x); As[r][k2 + 1] = f2tf(av.y);
    }
    __syncthreads();
    {
        uint2 b_ir = *(const uint2*)&Wih0p[((     nbB) * 32 + lane) * 2];
        uint2 b_iz = *(const uint2*)&Wih0p[((32 + nbB) * 32 + lane) * 2];
        uint2 b_in = *(const uint2*)&Wih0p[((64 + nbB) * 32 + lane) * 2];
#pragma unroll
        for (int mf = 0; mf < 2; mf++) {
            int rb = wm * 32 + mf * 16 + g;
            uint32_t a[4];
            a[0] = As[rb][t4];
            a[1] = As[rb + 8][t4];
            a[2] = As[rb][t4 + 4];
            a[3] = As[rb + 8][t4 + 4];
            mma8(accR[mf],  a, b_ir.x, b_ir.y);
            mma8(accZ[mf],  a, b_iz.x, b_iz.y);
            mma8(accIN[mf], a, b_in.x, b_in.y);
        }
    }
    __syncthreads();

    // h path (K=256)
    for (int k0 = 0; k0 < 256; k0 += 16) {
        float4 hv = *(const float4*)&h_in[(m0 + lr) * 256 + k0 + lk];
        Hs[lr][lk + 0] = f2tf(hv.x); Hs[lr][lk + 1] = f2tf(hv.y);
        Hs[lr][lk + 2] = f2tf(hv.z); Hs[lr][lk + 3] = f2tf(hv.w);
        __syncthreads();

        uint32_t ah[2][2][4];
#pragma unroll
        for (int mf = 0; mf < 2; mf++) {
            int rb = wm * 32 + mf * 16 + g;
#pragma unroll
            for (int ks = 0; ks < 2; ks++) {
                ah[mf][ks][0] = Hs[rb][ks * 8 + t4];
                ah[mf][ks][1] = Hs[rb + 8][ks * 8 + t4];
                ah[mf][ks][2] = Hs[rb][ks * 8 + t4 + 4];
                ah[mf][ks][3] = Hs[rb + 8][ks * 8 + t4 + 4];
            }
        }

        int kb = k0 >> 4;
        {
            uint4 b_hr = ldfrag(Whhp,      nbB, kb, 16, lane);
            uint4 b_hz = ldfrag(Whhp, 32 + nbB, kb, 16, lane);
            uint4 b_hn = ldfrag(Whhp, 64 + nbB, kb, 16, lane);
#pragma unroll
            for (int mf = 0; mf < 2; mf++) {
                mma8(accR[mf],  ah[mf][0], b_hr.x, b_hr.y);
                mma8(accR[mf],  ah[mf][1], b_hr.z, b_hr.w);
                mma8(accZ[mf],  ah[mf][0], b_hz.x, b_hz.y);
                mma8(accZ[mf],  ah[mf][1], b_hz.z, b_hz.w);
                mma8(accHN[mf], ah[mf][0], b_hn.x, b_hn.y);
                mma8(accHN[mf], ah[mf][1], b_hn.z, b_hn.w);
            }
        }
        __syncthreads();
    }

#pragma unroll
    for (int mf = 0; mf < 2; mf++)
#pragma unroll
        for (int rix = 0; rix < 4; rix++) {
            int row = m0 + wm * 32 + mf * 16 + g + 8 * (rix >> 1);
            int col = c0b + wn * 8 + t4 * 2 + (rix & 1);
            float r = sigm(accR[mf][rix] + bih[col] + bhh[col]);
            float z = sigm(accZ[mf][rix] + bih[col + 256] + bhh[col + 256]);
            float n = tanhf(accIN[mf][rix] + bih[col + 512] +
                            r * (accHN[mf][rix] + bhh[col + 512]));
            float hold = h_in[row * 256 + col];
            h_out[row * 256 + col] = (1.0f - z) * n + z * hold;
        }
}

// ---------------- logits + softmax ----------------
__global__ __launch_bounds__(256) void k_logits(
    const float* __restrict__ h, const float* __restrict__ Wa,
    const float* __restrict__ ba, float* __restrict__ out,
    float* __restrict__ a_next, int t)
{
    __shared__ float hs[32][257];
    __shared__ float Was[8][257];

    const int tid = threadIdx.x;
    const int rb0 = blockIdx.x * 32;

#pragma unroll
    for (int i = 0; i < 8; i++) {
        int idx = i * 256 + tid;
        int j = idx >> 8, k = idx & 255;
        Was[j][k] = Wa[j * 256 + k];
    }
#pragma unroll
    for (int i = 0; i < 32; i++) {
        int idx = i * 256 + tid;
        int r = idx >> 8, k = idx & 255;
        hs[r][k] = h[(rb0 + r) * 256 + k];
    }
    __syncthreads();

    const int r = tid >> 3, j = tid & 7;
    float s0 = 0.0f, s1 = 0.0f, s2 = 0.0f, s3 = 0.0f;
#pragma unroll 8
    for (int k = 0; k < 256; k += 4) {
        s0 += hs[r][k + 0] * Was[j][k + 0];
        s1 += hs[r][k + 1] * Was[j][k + 1];
        s2 += hs[r][k + 2] * Was[j][k + 2];
        s3 += hs[r][k + 3] * Was[j][k + 3];
    }
    float acc = (s0 + s1) + (s2 + s3) + ba[j];

    out[(rb0 + r) * (HOR * ACT) + t * ACT + j] = acc;

    float m = acc;
#pragma unroll
    for (int o = 4; o; o >>= 1) m = fmaxf(m, __shfl_xor_sync(0xffffffffu, m, o));
    float e = expf(acc - m);
    float s = e;
#pragma unroll
    for (int o = 4; o; o >>= 1) s += __shfl_xor_sync(0xffffffffu, s, o);
    a_next[(rb0 + r) * ACT + j] = e / s;
}

// ---------------- host ----------------
extern "C" void kernel_launch(void* const* d_in, const int* in_sizes, int n_in,
                              void* d_out, int out_size)
{
    const float* s0    = (const float*)d_in[0];
    const float* s1    = (const float*)d_in[1];
    const float* W1    = (const float*)d_in[3];
    const float* b1    = (const float*)d_in[4];
    const float* lng   = (const float*)d_in[5];
    const float* lnb   = (const float*)d_in[6];
    const float* W2    = (const float*)d_in[7];
    const float* b2    = (const float*)d_in[8];
    const float* Wih0  = (const float*)d_in[9];
    const float* Whh0  = (const float*)d_in[10];
    const float* bih0  = (const float*)d_in[11];
    const float* bhh0  = (const float*)d_in[12];
    const float* Wih1  = (const float*)d_in[13];
    const float* Whh1  = (const float*)d_in[14];
    const float* bih1  = (const float*)d_in[15];
    const float* bhh1  = (const float*)d_in[16];
    const float* Wa    = (const float*)d_in[17];
    const float* ba    = (const float*)d_in[18];
    const float* Winit = (const float*)d_in[19];
    const float* binit = (const float*)d_in[20];
    float* out = (float*)d_out;

    float *initbuf, *h0b, *h1b, *a0, *a1;
    uint32_t *W1p, *W2p, *Winitp, *Wih1p, *Whh1p, *Whh0p, *Wih0p;
    cudaGetSymbolAddress((void**)&initbuf, g_init);
    cudaGetSymbolAddress((void**)&h0b, g_h0b);
    cudaGetSymbolAddress((void**)&h1b, g_h1b);
    cudaGetSymbolAddress((void**)&a0, g_a0);
    cudaGetSymbolAddress((void**)&a1, g_a1);
    cudaGetSymbolAddress((void**)&W1p, g_W1p);
    cudaGetSymbolAddress((void**)&W2p, g_W2p);
    cudaGetSymbolAddress((void**)&Winitp, g_Winitp);
    cudaGetSymbolAddress((void**)&Wih1p, g_Wih1p);
    cudaGetSymbolAddress((void**)&Whh1p, g_Whh1p);
    cudaGetSymbolAddress((void**)&Whh0p, g_Whh0p);
    cudaGetSymbolAddress((void**)&Wih0p, g_Wih0p);

    static int attrs_set = 0;
    const int MLP_SMEM = (8448 + 8320) * 4;
    if (!attrs_set) {
        cudaFuncSetAttribute(k_mlp, cudaFuncAttributeMaxDynamicSharedMemorySize, MLP_SMEM);
        attrs_set = 1;
    }

    // launch 1: fused pack + a0 zero
    k_pack_all<<<(PK_TOT + 255) / 256, 256>>>(W1, W2, Winit, Wih1, Whh1, Whh0, Wih0, a0);

    // launch 2: fused prologue MLP
    k_mlp<<<BATCH / 32, 256, MLP_SMEM>>>(s0, s1, W1p, b1, lng, lnb,
                                         W2p, b2, Winitp, binit, initbuf);

    float* h0bufs[2] = {initbuf, h0b};
    float* h1bufs[2] = {initbuf + BATCH * HID, h1b};
    float* abufs[2]  = {a0, a1};

    // launch 3: gru0(t=0); launch 4: gru1(t=0)  <- profiled slot
    for (int t = 0; t < HOR; t++) {
        int cur = t & 1, nxt = 1 - cur;
        k_gru0_mma<<<dim3(8, BATCH / 64), 256>>>(abufs[cur], h0bufs[cur],
                                                 Wih0p, Whh0p, bih0, bhh0, h0bufs[nxt]);
        k_gru1_mma<<<dim3(8, BATCH / 64), 256>>>(h0bufs[nxt], h1bufs[cur],
                                                 Wih1p, Whh1p, bih1, bhh1, h1bufs[nxt]);
        k_logits<<<BATCH / 32, 256>>>(h1bufs[nxt], Wa, ba, out, abufs[nxt], t);
    }
}

// round 16
// speedup vs baseline: 1.8198x; 1.4263x over previous
#include <cuda_runtime.h>
#include <cuda_fp16.h>
#include <math.h>
#include <stdint.h>

#define BATCH 32768
#define SDIM 512
#define HID 256
#define ACT 8
#define HOR 10

// ---------------- scratch (device globals; no allocation) ----------------
__device__ float g_init[BATCH * 2 * HID];
__device__ float g_h0b[BATCH * HID];
__device__ float g_h1b[BATCH * HID];
__device__ float g_a0[BATCH * ACT];
__device__ float g_a1[BATCH * ACT];

// packed weights: tf32 for MLP + gru0 x-path, fp16x2 for GRU h/x matrices
__device__ uint32_t g_W1p[256 * 1024];
__device__ uint32_t g_W2p[256 * 256];
__device__ uint32_t g_Winitp[512 * 256];
__device__ uint32_t g_Wih1h[768 * 128];   // fp16x2: N*K/2 words
__device__ uint32_t g_Whh1h[768 * 128];
__device__ uint32_t g_Whh0h[768 * 128];
__device__ uint32_t g_Wih0p[768 * 8];     // tf32, K=8

// ---------------- helpers ----------------
__device__ __forceinline__ uint32_t f2tf(float f) {
    uint32_t u;
    asm("cvt.rna.tf32.f32 %0, %1;" : "=r"(u) : "f"(f));
    return u;
}

__device__ __forceinline__ uint32_t f2h2(float a, float b) {
    __half2 h = __floats2half2_rn(a, b);
    return *(uint32_t*)&h;
}

__device__ __forceinline__ void mma8(float c[4], const uint32_t a[4],
                                     uint32_t b0, uint32_t b1) {
    asm volatile(
        "mma.sync.aligned.m16n8k8.row.col.f32.tf32.tf32.f32 "
        "{%0,%1,%2,%3}, {%4,%5,%6,%7}, {%8,%9}, {%0,%1,%2,%3};"
        : "+f"(c[0]), "+f"(c[1]), "+f"(c[2]), "+f"(c[3])
        : "r"(a[0]), "r"(a[1]), "r"(a[2]), "r"(a[3]), "r"(b0), "r"(b1));
}

__device__ __forceinline__ void mma16(float c[4], const uint32_t a[4],
                                      uint32_t b0, uint32_t b1) {
    asm volatile(
        "mma.sync.aligned.m16n8k16.row.col.f32.f16.f16.f32 "
        "{%0,%1,%2,%3}, {%4,%5,%6,%7}, {%8,%9}, {%0,%1,%2,%3};"
        : "+f"(c[0]), "+f"(c[1]), "+f"(c[2]), "+f"(c[3])
        : "r"(a[0]), "r"(a[1]), "r"(a[2]), "r"(a[3]), "r"(b0), "r"(b1));
}

__device__ __forceinline__ float sigm(float x) {
    return 1.0f / (1.0f + expf(-x));
}

// tf32 fragment load: Wp layout [nb][kb][lane][4]
__device__ __forceinline__ uint4 ldfrag(const uint32_t* __restrict__ Wp,
                                        int nb, int kb, int KB, int lane) {
    return *(const uint4*)&Wp[((nb * KB + kb) * 32 + lane) * 4];
}

// fp16 fragment load: Wp layout [nb][kb16][lane][2]
__device__ __forceinline__ uint2 ldfragh(const uint32_t* __restrict__ Wp,
                                         int nb, int kb, int lane) {
    return *(const uint2*)&Wp[((nb * 16 + kb) * 32 + lane) * 2];
}

// ---------------- fused pack + zero kernel ----------------
__device__ __forceinline__ void pack_one(const float* __restrict__ W,
                                         uint32_t* __restrict__ Wp, int K, int i) {
    int KB = K >> 4;
    int q = i & 3;
    int lane = (i >> 2) & 31;
    int t = i >> 7;
    int kb = t % KB, nb = t / KB;
    int col = nb * 8 + (lane >> 2);
    int k = kb * 16 + q * 4 + (lane & 3);
    Wp[i] = f2tf(W[col * K + k]);
}

// fp16x2 pack, K=256: i = ((nb*16+kb)*32+lane)*2 + r
__device__ __forceinline__ void pack_h2(const float* __restrict__ W,
                                        uint32_t* __restrict__ Wp, int i) {
    int r = i & 1;
    int lane = (i >> 1) & 31;
    int t = i >> 6;
    int kb = t & 15, nb = t >> 4;
    int col = nb * 8 + (lane >> 2);
    int k = kb * 16 + r * 8 + (lane & 3) * 2;
    Wp[i] = f2h2(W[col * 256 + k], W[col * 256 + k + 1]);
}

#define PK_S0 262144
#define PK_S1 (PK_S0 + 65536)
#define PK_S2 (PK_S1 + 131072)
#define PK_S3 (PK_S2 + 98304)
#define PK_S4 (PK_S3 + 98304)
#define PK_S5 (PK_S4 + 98304)
#define PK_S6 (PK_S5 + 6144)
#define PK_TOT (PK_S6 + 262144)

__global__ void k_pack_all(const float* __restrict__ W1, const float* __restrict__ W2,
                           const float* __restrict__ Winit, const float* __restrict__ Wih1,
                           const float* __restrict__ Whh1, const float* __restrict__ Whh0,
                           const float* __restrict__ Wih0, float* __restrict__ a0)
{
    int i = blockIdx.x * blockDim.x + threadIdx.x;
    if (i >= PK_TOT) return;
    if (i < PK_S0)      { pack_one(W1,    g_W1p,    1024, i); }
    else if (i < PK_S1) { pack_one(W2,    g_W2p,    256,  i - PK_S0); }
    else if (i < PK_S2) { pack_one(Winit, g_Winitp, 256,  i - PK_S1); }
    else if (i < PK_S3) { pack_h2(Wih1, g_Wih1h, i - PK_S2); }
    else if (i < PK_S4) { pack_h2(Whh1, g_Whh1h, i - PK_S3); }
    else if (i < PK_S5) { pack_h2(Whh0, g_Whh0h, i - PK_S4); }
    else if (i < PK_S6) {
        int j = i - PK_S5;
        int q = j & 1;
        int lane = (j >> 1) & 31;
        int nb = j >> 6;
        int col = nb * 8 + (lane >> 2);
        int k = q * 4 + (lane & 3);
        g_Wih0p[j] = f2tf(Wih0[col * 8 + k]);
    } else {
        a0[i - PK_S6] = 0.0f;
    }
}

// ---------------- fused MLP (exact R12) ----------------
__global__ __launch_bounds__(256) void k_mlp(
    const float* __restrict__ s0, const float* __restrict__ s1,
    const uint32_t* __restrict__ W1p, const float* __restrict__ b1,
    const float* __restrict__ gam, const float* __restrict__ bet,
    const uint32_t* __restrict__ W2p, const float* __restrict__ b2,
    const uint32_t* __restrict__ Winitp, const float* __restrict__ binit,
    float* __restrict__ initout)
{
    extern __shared__ __align__(16) uint32_t DSM[];
    uint32_t* SB = DSM;
    uint32_t* H1 = DSM + 8448;

    const int tid  = threadIdx.x;
    const int rowBase = blockIdx.x * 32;
    const int warp = tid >> 5, lane = tid & 31;
    const int wm = warp >> 2, wn = warp & 3;
    const int g  = lane >> 2, t4 = lane & 3;

    float acc[8][4];
#pragma unroll
    for (int i = 0; i < 8; i++)
#pragma unroll
        for (int j = 0; j < 4; j++) acc[i][j] = 0.0f;

    for (int k0 = 0; k0 < 1024; k0 += 16) {
        if (tid < 128) {
            int r = tid >> 2, lk = (tid & 3) * 4;
            int k = k0 + lk;
            float4 v;
            if (k < 512) v = *(const float4*)&s0[(rowBase + r) * 512 + k];
            else         v = *(const float4*)&s1[(rowBase + r) * 512 + (k - 512)];
            uint32_t* Xp = &SB[r * 20 + lk];
            Xp[0] = f2tf(v.x); Xp[1] = f2tf(v.y); Xp[2] = f2tf(v.z); Xp[3] = f2tf(v.w);
        }
        __syncthreads();
        uint32_t a[2][4];
#pragma unroll
        for (int ks = 0; ks < 2; ks++) {
            a[ks][0] = SB[(wm * 16 + g) * 20 + ks * 8 + t4];
            a[ks][1] = SB[(wm * 16 + g + 8) * 20 + ks * 8 + t4];
            a[ks][2] = SB[(wm * 16 + g) * 20 + ks * 8 + t4 + 4];
            a[ks][3] = SB[(wm * 16 + g + 8) * 20 + ks * 8 + t4 + 4];
        }
        int kb = k0 >> 4;
#pragma unroll
        for (int nt = 0; nt < 8; nt++) {
            uint4 b = ldfrag(W1p, wn * 8 + nt, kb, 64, lane);
            mma8(acc[nt], a[0], b.x, b.y);
            mma8(acc[nt], a[1], b.z, b.w);
        }
        __syncthreads();
    }

    float* Cs = (float*)SB;
#pragma unroll
    for (int nt = 0; nt < 8; nt++)
#pragma unroll
        for (int rix = 0; rix < 4; rix++) {
            int row = wm * 16 + g + 8 * (rix >> 1);
            int col = wn * 64 + nt * 8 + t4 * 2 + (rix & 1);
            Cs[row * 264 + col] = acc[nt][rix];
        }
    __syncthreads();

    for (int rr = 0; rr < 4; rr++) {
        int row = warp * 4 + rr;
        float v[8];
        float sum = 0.0f, sq = 0.0f;
#pragma unroll
        for (int i = 0; i < 8; i++) {
            int c = lane + 32 * i;
            v[i] = Cs[row * 264 + c] + b1[c];
            sum += v[i];
            sq  += v[i] * v[i];
        }
#pragma unroll
        for (int o = 16; o; o >>= 1) {
            sum += __shfl_xor_sync(0xffffffffu, sum, o);
            sq  += __shfl_xor_sync(0xffffffffu, sq, o);
        }
        float mean = sum * (1.0f / 256.0f);
        float var  = sq * (1.0f / 256.0f) - mean * mean;
        float rstd = rsqrtf(var + 1e-5f);
#pragma unroll
        for (int i = 0; i < 8; i++) {
            int c = lane + 32 * i;
            float o = (v[i] - mean) * rstd * gam[c] + bet[c];
            H1[row * 260 + c] = f2tf(fmaxf(o, 0.0f));
        }
    }
    __syncthreads();

#pragma unroll
    for (int i = 0; i < 8; i++)
#pragma unroll
        for (int j = 0; j < 4; j++) acc[i][j] = 0.0f;

    for (int kb = 0; kb < 16; kb++) {
        uint32_t a[2][4];
#pragma unroll
        for (int ks = 0; ks < 2; ks++) {
            int kc = kb * 16 + ks * 8;
            a[ks][0] = H1[(wm * 16 + g) * 260 + kc + t4];
            a[ks][1] = H1[(wm * 16 + g + 8) * 260 + kc + t4];
            a[ks][2] = H1[(wm * 16 + g) * 260 + kc + t4 + 4];
            a[ks][3] = H1[(wm * 16 + g + 8) * 260 + kc + t4 + 4];
        }
#pragma unroll
        for (int nt = 0; nt < 8; nt++) {
            uint4 b = ldfrag(W2p, wn * 8 + nt, kb, 16, lane);
            mma8(acc[nt], a[0], b.x, b.y);
            mma8(acc[nt], a[1], b.z, b.w);
        }
    }
#pragma unroll
    for (int nt = 0; nt < 8; nt++)
#pragma unroll
        for (int rix = 0; rix < 4; rix++) {
            int row = wm * 16 + g + 8 * (rix >> 1);
            int col = wn * 64 + nt * 8 + t4 * 2 + (rix & 1);
            SB[row * 260 + col] = f2tf(fmaxf(acc[nt][rix] + b2[col], 0.0f));
        }
    __syncthreads();

    for (int nh = 0; nh < 2; nh++) {
#pragma unroll
        for (int i = 0; i < 8; i++)
#pragma unroll
            for (int j = 0; j < 4; j++) acc[i][j] = 0.0f;

        for (int kb = 0; kb < 16; kb++) {
            uint32_t a[2][4];
#pragma unroll
            for (int ks = 0; ks < 2; ks++) {
                int kc = kb * 16 + ks * 8;
                a[ks][0] = SB[(wm * 16 + g) * 260 + kc + t4];
                a[ks][1] = SB[(wm * 16 + g + 8) * 260 + kc + t4];
                a[ks][2] = SB[(wm * 16 + g) * 260 + kc + t4 + 4];
                a[ks][3] = SB[(wm * 16 + g + 8) * 260 + kc + t4 + 4];
            }
#pragma unroll
            for (int nt = 0; nt < 8; nt++) {
                uint4 b = ldfrag(Winitp, nh * 32 + wn * 8 + nt, kb, 16, lane);
                mma8(acc[nt], a[0], b.x, b.y);
                mma8(acc[nt], a[1], b.z, b.w);
            }
        }
#pragma unroll
        for (int nt = 0; nt < 8; nt++)
#pragma unroll
            for (int rix = 0; rix < 4; rix++) {
                int row = wm * 16 + g + 8 * (rix >> 1);
                int col = wn * 64 + nt * 8 + t4 * 2 + (rix & 1);
                initout[(rowBase + row) * 512 + nh * 256 + col] =
                    acc[nt][rix] + binit[nh * 256 + col];
            }
    }
}

// ---------------- GRU cell 1: fp16 m16n8k16, R12 geometry (BM=64, BN=64, warp 32x16) ----------------
__global__ __launch_bounds__(256, 2) void k_gru1_mma(
    const float* __restrict__ x_in, const float* __restrict__ h_in,
    const uint32_t* __restrict__ Wihh, const uint32_t* __restrict__ Whhh,
    const float* __restrict__ bih, const float* __restrict__ bhh,
    float* __restrict__ h_out)
{
    __shared__ __align__(16) uint32_t Xs[64][12];   // 8 half2 words + pad
    __shared__ __align__(16) uint32_t Hs[64][12];

    const int tid = threadIdx.x;
    const int m0 = blockIdx.y * 64, c0b = blockIdx.x * 64;
    const int warp = tid >> 5, lane = tid & 31;
    const int wm = warp >> 2, wn = warp & 3;
    const int g = lane >> 2, t4 = lane & 3;
    const int lr = tid >> 2, lk = (tid & 3) * 4, wlk = (tid & 3) * 2;

    float accR[2][2][4], accZ[2][2][4], accIN[2][2][4], accHN[2][2][4];
#pragma unroll
    for (int mf = 0; mf < 2; mf++)
#pragma unroll
        for (int nt = 0; nt < 2; nt++)
#pragma unroll
            for (int j = 0; j < 4; j++) {
                accR[mf][nt][j] = 0.0f; accZ[mf][nt][j] = 0.0f;
                accIN[mf][nt][j] = 0.0f; accHN[mf][nt][j] = 0.0f;
            }

    for (int kt = 0; kt < 16; kt++) {
        float4 xv = *(const float4*)&x_in[(m0 + lr) * 256 + kt * 16 + lk];
        float4 hv = *(const float4*)&h_in[(m0 + lr) * 256 + kt * 16 + lk];
        Xs[lr][wlk]     = f2h2(xv.x, xv.y);
        Xs[lr][wlk + 1] = f2h2(xv.z, xv.w);
        Hs[lr][wlk]     = f2h2(hv.x, hv.y);
        Hs[lr][wlk + 1] = f2h2(hv.z, hv.w);
        __syncthreads();

        uint32_t ax[2][4], ah[2][4];
#pragma unroll
        for (int mf = 0; mf < 2; mf++) {
            int rb = wm * 32 + mf * 16 + g;
            ax[mf][0] = Xs[rb][t4];
            ax[mf][1] = Xs[rb + 8][t4];
            ax[mf][2] = Xs[rb][t4 + 4];
            ax[mf][3] = Xs[rb + 8][t4 + 4];
            ah[mf][0] = Hs[rb][t4];
            ah[mf][1] = Hs[rb + 8][t4];
            ah[mf][2] = Hs[rb][t4 + 4];
            ah[mf][3] = Hs[rb + 8][t4 + 4];
        }

#pragma unroll
        for (int nt = 0; nt < 2; nt++) {
            int nbB = (c0b + wn * 16 + nt * 8) >> 3;
            uint2 b_ir = ldfragh(Wihh,      nbB, kt, lane);
            uint2 b_iz = ldfragh(Wihh, 32 + nbB, kt, lane);
            uint2 b_in = ldfragh(Wihh, 64 + nbB, kt, lane);
            uint2 b_hr = ldfragh(Whhh,      nbB, kt, lane);
            uint2 b_hz = ldfragh(Whhh, 32 + nbB, kt, lane);
            uint2 b_hn = ldfragh(Whhh, 64 + nbB, kt, lane);
#pragma unroll
            for (int mf = 0; mf < 2; mf++) {
                mma16(accR[mf][nt],  ax[mf], b_ir.x, b_ir.y);
                mma16(accR[mf][nt],  ah[mf], b_hr.x, b_hr.y);
                mma16(accZ[mf][nt],  ax[mf], b_iz.x, b_iz.y);
                mma16(accZ[mf][nt],  ah[mf], b_hz.x, b_hz.y);
                mma16(accIN[mf][nt], ax[mf], b_in.x, b_in.y);
                mma16(accHN[mf][nt], ah[mf], b_hn.x, b_hn.y);
            }
        }
        __syncthreads();
    }

#pragma unroll
    for (int mf = 0; mf < 2; mf++)
#pragma unroll
        for (int nt = 0; nt < 2; nt++)
#pragma unroll
            for (int rix = 0; rix < 4; rix++) {
                int row = m0 + wm * 32 + mf * 16 + g + 8 * (rix >> 1);
                int col = c0b + wn * 16 + nt * 8 + t4 * 2 + (rix & 1);
                float r = sigm(accR[mf][nt][rix] + bih[col] + bhh[col]);
                float z = sigm(accZ[mf][nt][rix] + bih[col + 256] + bhh[col + 256]);
                float n = tanhf(accIN[mf][nt][rix] + bih[col + 512] +
                                r * (accHN[mf][nt][rix] + bhh[col + 512]));
                float hold = h_in[row * 256 + col];
                h_out[row * 256 + col] = (1.0f - z) * n + z * hold;
            }
}

// ---------------- GRU cell 0: tf32 x-path (K=8) + fp16 h-path ----------------
__global__ __launch_bounds__(256, 2) void k_gru0_mma(
    const float* __restrict__ a_in, const float* __restrict__ h_in,
    const uint32_t* __restrict__ Wih0p, const uint32_t* __restrict__ Whhh,
    const float* __restrict__ bih, const float* __restrict__ bhh,
    float* __restrict__ h_out)
{
    __shared__ __align__(16) uint32_t Hs[64][12];
    __shared__ __align__(16) uint32_t As[64][12];

    const int tid = threadIdx.x;
    const int m0 = blockIdx.y * 64, c0b = blockIdx.x * 64;
    const int warp = tid >> 5, lane = tid & 31;
    const int wm = warp >> 2, wn = warp & 3;
    const int g = lane >> 2, t4 = lane & 3;
    const int lr = tid >> 2, lk = (tid & 3) * 4, wlk = (tid & 3) * 2;

    float accR[2][2][4], accZ[2][2][4], accIN[2][2][4], accHN[2][2][4];
#pragma unroll
    for (int mf = 0; mf < 2; mf++)
#pragma unroll
        for (int nt = 0; nt < 2; nt++)
#pragma unroll
            for (int j = 0; j < 4; j++) {
                accR[mf][nt][j] = 0.0f; accZ[mf][nt][j] = 0.0f;
                accIN[mf][nt][j] = 0.0f; accHN[mf][nt][j] = 0.0f;
            }

    // x path (K=8, tf32)
    {
        int r = tid >> 2, k2 = (tid & 3) * 2;
        float2 av = *(const float2*)&a_in[(m0 + r) * 8 + k2];
        As[r][k2] = f2tf(av.x); As[r][k2 + 1] = f2tf(av.y);
    }
    __syncthreads();
    {
        uint32_t a[2][4];
#pragma unroll
        for (int mf = 0; mf < 2; mf++) {
            int rb = wm * 32 + mf * 16 + g;
            a[mf][0] = As[rb][t4];
            a[mf][1] = As[rb + 8][t4];
            a[mf][2] = As[rb][t4 + 4];
            a[mf][3] = As[rb + 8][t4 + 4];
        }
#pragma unroll
        for (int nt = 0; nt < 2; nt++) {
            int nbB = (c0b + wn * 16 + nt * 8) >> 3;
            uint2 b_ir = *(const uint2*)&Wih0p[((     nbB) * 32 + lane) * 2];
            uint2 b_iz = *(const uint2*)&Wih0p[((32 + nbB) * 32 + lane) * 2];
            uint2 b_in = *(const uint2*)&Wih0p[((64 + nbB) * 32 + lane) * 2];
#pragma unroll
            for (int mf = 0; mf < 2; mf++) {
                mma8(accR[mf][nt],  a[mf], b_ir.x, b_ir.y);
                mma8(accZ[mf][nt],  a[mf], b_iz.x, b_iz.y);
                mma8(accIN[mf][nt], a[mf], b_in.x, b_in.y);
            }
        }
    }
    __syncthreads();

    // h path (K=256, fp16)
    for (int kt = 0; kt < 16; kt++) {
        float4 hv = *(const float4*)&h_in[(m0 + lr) * 256 + kt * 16 + lk];
        Hs[lr][wlk]     = f2h2(hv.x, hv.y);
        Hs[lr][wlk + 1] = f2h2(hv.z, hv.w);
        __syncthreads();

        uint32_t ah[2][4];
#pragma unroll
        for (int mf = 0; mf < 2; mf++) {
            int rb = wm * 32 + mf * 16 + g;
            ah[mf][0] = Hs[rb][t4];
            ah[mf][1] = Hs[rb + 8][t4];
            ah[mf][2] = Hs[rb][t4 + 4];
            ah[mf][3] = Hs[rb + 8][t4 + 4];
        }

#pragma unroll
        for (int nt = 0; nt < 2; nt++) {
            int nbB = (c0b + wn * 16 + nt * 8) >> 3;
            uint2 b_hr = ldfragh(Whhh,      nbB, kt, lane);
            uint2 b_hz = ldfragh(Whhh, 32 + nbB, kt, lane);
            uint2 b_hn = ldfragh(Whhh, 64 + nbB, kt, lane);
#pragma unroll
            for (int mf = 0; mf < 2; mf++) {
                mma16(accR[mf][nt],  ah[mf], b_hr.x, b_hr.y);
                mma16(accZ[mf][nt],  ah[mf], b_hz.x, b_hz.y);
                mma16(accHN[mf][nt], ah[mf], b_hn.x, b_hn.y);
            }
        }
        __syncthreads();
    }

#pragma unroll
    for (int mf = 0; mf < 2; mf++)
#pragma unroll
        for (int nt = 0; nt < 2; nt++)
#pragma unroll
            for (int rix = 0; rix < 4; rix++) {
                int row = m0 + wm * 32 + mf * 16 + g + 8 * (rix >> 1);
                int col = c0b + wn * 16 + nt * 8 + t4 * 2 + (rix & 1);
                float r = sigm(accR[mf][nt][rix] + bih[col] + bhh[col]);
                float z = sigm(accZ[mf][nt][rix] + bih[col + 256] + bhh[col + 256]);
                float n = tanhf(accIN[mf][nt][rix] + bih[col + 512] +
                                r * (accHN[mf][nt][rix] + bhh[col + 512]));
                float hold = h_in[row * 256 + col];
                h_out[row * 256 + col] = (1.0f - z) * n + z * hold;
            }
}

// ---------------- logits + softmax ----------------
__global__ __launch_bounds__(256) void k_logits(
    const float* __restrict__ h, const float* __restrict__ Wa,
    const float* __restrict__ ba, float* __restrict__ out,
    float* __restrict__ a_next, int t)
{
    __shared__ float hs[32][257];
    __shared__ float Was[8][257];

    const int tid = threadIdx.x;
    const int rb0 = blockIdx.x * 32;

#pragma unroll
    for (int i = 0; i < 8; i++) {
        int idx = i * 256 + tid;
        int j = idx >> 8, k = idx & 255;
        Was[j][k] = Wa[j * 256 + k];
    }
#pragma unroll
    for (int i = 0; i < 32; i++) {
        int idx = i * 256 + tid;
        int r = idx >> 8, k = idx & 255;
        hs[r][k] = h[(rb0 + r) * 256 + k];
    }
    __syncthreads();

    const int r = tid >> 3, j = tid & 7;
    float s0 = 0.0f, s1 = 0.0f, s2 = 0.0f, s3 = 0.0f;
#pragma unroll 8
    for (int k = 0; k < 256; k += 4) {
        s0 += hs[r][k + 0] * Was[j][k + 0];
        s1 += hs[r][k + 1] * Was[j][k + 1];
        s2 += hs[r][k + 2] * Was[j][k + 2];
        s3 += hs[r][k + 3] * Was[j][k + 3];
    }
    float acc = (s0 + s1) + (s2 + s3) + ba[j];

    out[(rb0 + r) * (HOR * ACT) + t * ACT + j] = acc;

    float m = acc;
#pragma unroll
    for (int o = 4; o; o >>= 1) m = fmaxf(m, __shfl_xor_sync(0xffffffffu, m, o));
    float e = expf(acc - m);
    float s = e;
#pragma unroll
    for (int o = 4; o; o >>= 1) s += __shfl_xor_sync(0xffffffffu, s, o);
    a_next[(rb0 + r) * ACT + j] = e / s;
}

// ---------------- host ----------------
extern "C" void kernel_launch(void* const* d_in, const int* in_sizes, int n_in,
                              void* d_out, int out_size)
{
    const float* s0    = (const float*)d_in[0];
    const float* s1    = (const float*)d_in[1];
    const float* W1    = (const float*)d_in[3];
    const float* b1    = (const float*)d_in[4];
    const float* lng   = (const float*)d_in[5];
    const float* lnb   = (const float*)d_in[6];
    const float* W2    = (const float*)d_in[7];
    const float* b2    = (const float*)d_in[8];
    const float* Wih0  = (const float*)d_in[9];
    const float* Whh0  = (const float*)d_in[10];
    const float* bih0  = (const float*)d_in[11];
    const float* bhh0  = (const float*)d_in[12];
    const float* Wih1  = (const float*)d_in[13];
    const float* Whh1  = (const float*)d_in[14];
    const float* bih1  = (const float*)d_in[15];
    const float* bhh1  = (const float*)d_in[16];
    const float* Wa    = (const float*)d_in[17];
    const float* ba    = (const float*)d_in[18];
    const float* Winit = (const float*)d_in[19];
    const float* binit = (const float*)d_in[20];
    float* out = (float*)d_out;

    float *initbuf, *h0b, *h1b, *a0, *a1;
    uint32_t *W1p, *W2p, *Winitp, *Wih1h, *Whh1h, *Whh0h, *Wih0p;
    cudaGetSymbolAddress((void**)&initbuf, g_init);
    cudaGetSymbolAddress((void**)&h0b, g_h0b);
    cudaGetSymbolAddress((void**)&h1b, g_h1b);
    cudaGetSymbolAddress((void**)&a0, g_a0);
    cudaGetSymbolAddress((void**)&a1, g_a1);
    cudaGetSymbolAddress((void**)&W1p, g_W1p);
    cudaGetSymbolAddress((void**)&W2p, g_W2p);
    cudaGetSymbolAddress((void**)&Winitp, g_Winitp);
    cudaGetSymbolAddress((void**)&Wih1h, g_Wih1h);
    cudaGetSymbolAddress((void**)&Whh1h, g_Whh1h);
    cudaGetSymbolAddress((void**)&Whh0h, g_Whh0h);
    cudaGetSymbolAddress((void**)&Wih0p, g_Wih0p);

    static int attrs_set = 0;
    const int MLP_SMEM = (8448 + 8320) * 4;
    if (!attrs_set) {
        cudaFuncSetAttribute(k_mlp, cudaFuncAttributeMaxDynamicSharedMemorySize, MLP_SMEM);
        attrs_set = 1;
    }

    // launch 1: fused pack + a0 zero
    k_pack_all<<<(PK_TOT + 255) / 256, 256>>>(W1, W2, Winit, Wih1, Whh1, Whh0, Wih0, a0);

    // launch 2: fused prologue MLP
    k_mlp<<<BATCH / 32, 256, MLP_SMEM>>>(s0, s1, W1p, b1, lng, lnb,
                                         W2p, b2, Winitp, binit, initbuf);

    float* h0bufs[2] = {initbuf, h0b};
    float* h1bufs[2] = {initbuf + BATCH * HID, h1b};
    float* abufs[2]  = {a0, a1};

    // launch 3: gru0(t=0); launch 4: gru1(t=0)  <- profiled slot
    for (int t = 0; t < HOR; t++) {
        int cur = t & 1, nxt = 1 - cur;
        k_gru0_mma<<<dim3(4, BATCH / 64), 256>>>(abufs[cur], h0bufs[cur],
                                                 Wih0p, Whh0h, bih0, bhh0, h0bufs[nxt]);
        k_gru1_mma<<<dim3(4, BATCH / 64), 256>>>(h0bufs[nxt], h1bufs[cur],
                                                 Wih1h, Whh1h, bih1, bhh1, h1bufs[nxt]);
        k_logits<<<BATCH / 32, 256>>>(h1bufs[nxt], Wa, ba, out, abufs[nxt], t);
    }
}

// round 17
// speedup vs baseline: 1.9565x; 1.0752x over previous
#include <cuda_runtime.h>
#include <cuda_fp16.h>
#include <math.h>
#include <stdint.h>

#define BATCH 32768
#define SDIM 512
#define HID 256
#define ACT 8
#define HOR 10

// ---------------- scratch (device globals; no allocation) ----------------
__device__ float g_init[BATCH * 2 * HID];
__device__ float g_h0b[BATCH * HID];
__device__ float g_h1b[BATCH * HID];
__device__ float g_a0[BATCH * ACT];
__device__ float g_a1[BATCH * ACT];

// packed weights: tf32 for MLP + gru0 x-path, fp16x2 for GRU h/x matrices
__device__ uint32_t g_W1p[256 * 1024];
__device__ uint32_t g_W2p[256 * 256];
__device__ uint32_t g_Winitp[512 * 256];
__device__ uint32_t g_Wih1h[768 * 128];
__device__ uint32_t g_Whh1h[768 * 128];
__device__ uint32_t g_Whh0h[768 * 128];
__device__ uint32_t g_Wih0p[768 * 8];

// ---------------- helpers ----------------
__device__ __forceinline__ uint32_t f2tf(float f) {
    uint32_t u;
    asm("cvt.rna.tf32.f32 %0, %1;" : "=r"(u) : "f"(f));
    return u;
}

__device__ __forceinline__ uint32_t f2h2(float a, float b) {
    __half2 h = __floats2half2_rn(a, b);
    return *(uint32_t*)&h;
}

__device__ __forceinline__ void mma8(float c[4], const uint32_t a[4],
                                     uint32_t b0, uint32_t b1) {
    asm volatile(
        "mma.sync.aligned.m16n8k8.row.col.f32.tf32.tf32.f32 "
        "{%0,%1,%2,%3}, {%4,%5,%6,%7}, {%8,%9}, {%0,%1,%2,%3};"
        : "+f"(c[0]), "+f"(c[1]), "+f"(c[2]), "+f"(c[3])
        : "r"(a[0]), "r"(a[1]), "r"(a[2]), "r"(a[3]), "r"(b0), "r"(b1));
}

__device__ __forceinline__ void mma16(float c[4], const uint32_t a[4],
                                      uint32_t b0, uint32_t b1) {
    asm volatile(
        "mma.sync.aligned.m16n8k16.row.col.f32.f16.f16.f32 "
        "{%0,%1,%2,%3}, {%4,%5,%6,%7}, {%8,%9}, {%0,%1,%2,%3};"
        : "+f"(c[0]), "+f"(c[1]), "+f"(c[2]), "+f"(c[3])
        : "r"(a[0]), "r"(a[1]), "r"(a[2]), "r"(a[3]), "r"(b0), "r"(b1));
}

__device__ __forceinline__ float sigm(float x) {
    return 1.0f / (1.0f + expf(-x));
}

__device__ __forceinline__ uint4 ldfrag(const uint32_t* __restrict__ Wp,
                                        int nb, int kb, int KB, int lane) {
    return *(const uint4*)&Wp[((nb * KB + kb) * 32 + lane) * 4];
}

__device__ __forceinline__ uint2 ldfragh(const uint32_t* __restrict__ Wp,
                                         int nb, int kb, int lane) {
    return *(const uint2*)&Wp[((nb * 16 + kb) * 32 + lane) * 2];
}

// ---------------- fused pack + zero kernel ----------------
__device__ __forceinline__ void pack_one(const float* __restrict__ W,
                                         uint32_t* __restrict__ Wp, int K, int i) {
    int KB = K >> 4;
    int q = i & 3;
    int lane = (i >> 2) & 31;
    int t = i >> 7;
    int kb = t % KB, nb = t / KB;
    int col = nb * 8 + (lane >> 2);
    int k = kb * 16 + q * 4 + (lane & 3);
    Wp[i] = f2tf(W[col * K + k]);
}

__device__ __forceinline__ void pack_h2(const float* __restrict__ W,
                                        uint32_t* __restrict__ Wp, int i) {
    int r = i & 1;
    int lane = (i >> 1) & 31;
    int t = i >> 6;
    int kb = t & 15, nb = t >> 4;
    int col = nb * 8 + (lane >> 2);
    int k = kb * 16 + r * 8 + (lane & 3) * 2;
    Wp[i] = f2h2(W[col * 256 + k], W[col * 256 + k + 1]);
}

#define PK_S0 262144
#define PK_S1 (PK_S0 + 65536)
#define PK_S2 (PK_S1 + 131072)
#define PK_S3 (PK_S2 + 98304)
#define PK_S4 (PK_S3 + 98304)
#define PK_S5 (PK_S4 + 98304)
#define PK_S6 (PK_S5 + 6144)
#define PK_TOT (PK_S6 + 262144)

__global__ void k_pack_all(const float* __restrict__ W1, const float* __restrict__ W2,
                           const float* __restrict__ Winit, const float* __restrict__ Wih1,
                           const float* __restrict__ Whh1, const float* __restrict__ Whh0,
                           const float* __restrict__ Wih0, float* __restrict__ a0)
{
    int i = blockIdx.x * blockDim.x + threadIdx.x;
    if (i >= PK_TOT) return;
    if (i < PK_S0)      { pack_one(W1,    g_W1p,    1024, i); }
    else if (i < PK_S1) { pack_one(W2,    g_W2p,    256,  i - PK_S0); }
    else if (i < PK_S2) { pack_one(Winit, g_Winitp, 256,  i - PK_S1); }
    else if (i < PK_S3) { pack_h2(Wih1, g_Wih1h, i - PK_S2); }
    else if (i < PK_S4) { pack_h2(Whh1, g_Whh1h, i - PK_S3); }
    else if (i < PK_S5) { pack_h2(Whh0, g_Whh0h, i - PK_S4); }
    else if (i < PK_S6) {
        int j = i - PK_S5;
        int q = j & 1;
        int lane = (j >> 1) & 31;
        int nb = j >> 6;
        int col = nb * 8 + (lane >> 2);
        int k = q * 4 + (lane & 3);
        g_Wih0p[j] = f2tf(Wih0[col * 8 + k]);
    } else {
        a0[i - PK_S6] = 0.0f;
    }
}

// ---------------- fused MLP (exact R12) ----------------
__global__ __launch_bounds__(256) void k_mlp(
    const float* __restrict__ s0, const float* __restrict__ s1,
    const uint32_t* __restrict__ W1p, const float* __restrict__ b1,
    const float* __restrict__ gam, const float* __restrict__ bet,
    const uint32_t* __restrict__ W2p, const float* __restrict__ b2,
    const uint32_t* __restrict__ Winitp, const float* __restrict__ binit,
    float* __restrict__ initout)
{
    extern __shared__ __align__(16) uint32_t DSM[];
    uint32_t* SB = DSM;
    uint32_t* H1 = DSM + 8448;

    const int tid  = threadIdx.x;
    const int rowBase = blockIdx.x * 32;
    const int warp = tid >> 5, lane = tid & 31;
    const int wm = warp >> 2, wn = warp & 3;
    const int g  = lane >> 2, t4 = lane & 3;

    float acc[8][4];
#pragma unroll
    for (int i = 0; i < 8; i++)
#pragma unroll
        for (int j = 0; j < 4; j++) acc[i][j] = 0.0f;

    for (int k0 = 0; k0 < 1024; k0 += 16) {
        if (tid < 128) {
            int r = tid >> 2, lk = (tid & 3) * 4;
            int k = k0 + lk;
            float4 v;
            if (k < 512) v = *(const float4*)&s0[(rowBase + r) * 512 + k];
            else         v = *(const float4*)&s1[(rowBase + r) * 512 + (k - 512)];
            uint32_t* Xp = &SB[r * 20 + lk];
            Xp[0] = f2tf(v.x); Xp[1] = f2tf(v.y); Xp[2] = f2tf(v.z); Xp[3] = f2tf(v.w);
        }
        __syncthreads();
        uint32_t a[2][4];
#pragma unroll
        for (int ks = 0; ks < 2; ks++) {
            a[ks][0] = SB[(wm * 16 + g) * 20 + ks * 8 + t4];
            a[ks][1] = SB[(wm * 16 + g + 8) * 20 + ks * 8 + t4];
            a[ks][2] = SB[(wm * 16 + g) * 20 + ks * 8 + t4 + 4];
            a[ks][3] = SB[(wm * 16 + g + 8) * 20 + ks * 8 + t4 + 4];
        }
        int kb = k0 >> 4;
#pragma unroll
        for (int nt = 0; nt < 8; nt++) {
            uint4 b = ldfrag(W1p, wn * 8 + nt, kb, 64, lane);
            mma8(acc[nt], a[0], b.x, b.y);
            mma8(acc[nt], a[1], b.z, b.w);
        }
        __syncthreads();
    }

    float* Cs = (float*)SB;
#pragma unroll
    for (int nt = 0; nt < 8; nt++)
#pragma unroll
        for (int rix = 0; rix < 4; rix++) {
            int row = wm * 16 + g + 8 * (rix >> 1);
            int col = wn * 64 + nt * 8 + t4 * 2 + (rix & 1);
            Cs[row * 264 + col] = acc[nt][rix];
        }
    __syncthreads();

    for (int rr = 0; rr < 4; rr++) {
        int row = warp * 4 + rr;
        float v[8];
        float sum = 0.0f, sq = 0.0f;
#pragma unroll
        for (int i = 0; i < 8; i++) {
            int c = lane + 32 * i;
            v[i] = Cs[row * 264 + c] + b1[c];
            sum += v[i];
            sq  += v[i] * v[i];
        }
#pragma unroll
        for (int o = 16; o; o >>= 1) {
            sum += __shfl_xor_sync(0xffffffffu, sum, o);
            sq  += __shfl_xor_sync(0xffffffffu, sq, o);
        }
        float mean = sum * (1.0f / 256.0f);
        float var  = sq * (1.0f / 256.0f) - mean * mean;
        float rstd = rsqrtf(var + 1e-5f);
#pragma unroll
        for (int i = 0; i < 8; i++) {
            int c = lane + 32 * i;
            float o = (v[i] - mean) * rstd * gam[c] + bet[c];
            H1[row * 260 + c] = f2tf(fmaxf(o, 0.0f));
        }
    }
    __syncthreads();

#pragma unroll
    for (int i = 0; i < 8; i++)
#pragma unroll
        for (int j = 0; j < 4; j++) acc[i][j] = 0.0f;

    for (int kb = 0; kb < 16; kb++) {
        uint32_t a[2][4];
#pragma unroll
        for (int ks = 0; ks < 2; ks++) {
            int kc = kb * 16 + ks * 8;
            a[ks][0] = H1[(wm * 16 + g) * 260 + kc + t4];
            a[ks][1] = H1[(wm * 16 + g + 8) * 260 + kc + t4];
            a[ks][2] = H1[(wm * 16 + g) * 260 + kc + t4 + 4];
            a[ks][3] = H1[(wm * 16 + g + 8) * 260 + kc + t4 + 4];
        }
#pragma unroll
        for (int nt = 0; nt < 8; nt++) {
            uint4 b = ldfrag(W2p, wn * 8 + nt, kb, 16, lane);
            mma8(acc[nt], a[0], b.x, b.y);
            mma8(acc[nt], a[1], b.z, b.w);
        }
    }
#pragma unroll
    for (int nt = 0; nt < 8; nt++)
#pragma unroll
        for (int rix = 0; rix < 4; rix++) {
            int row = wm * 16 + g + 8 * (rix >> 1);
            int col = wn * 64 + nt * 8 + t4 * 2 + (rix & 1);
            SB[row * 260 + col] = f2tf(fmaxf(acc[nt][rix] + b2[col], 0.0f));
        }
    __syncthreads();

    for (int nh = 0; nh < 2; nh++) {
#pragma unroll
        for (int i = 0; i < 8; i++)
#pragma unroll
            for (int j = 0; j < 4; j++) acc[i][j] = 0.0f;

        for (int kb = 0; kb < 16; kb++) {
            uint32_t a[2][4];
#pragma unroll
            for (int ks = 0; ks < 2; ks++) {
                int kc = kb * 16 + ks * 8;
                a[ks][0] = SB[(wm * 16 + g) * 260 + kc + t4];
                a[ks][1] = SB[(wm * 16 + g + 8) * 260 + kc + t4];
                a[ks][2] = SB[(wm * 16 + g) * 260 + kc + t4 + 4];
                a[ks][3] = SB[(wm * 16 + g + 8) * 260 + kc + t4 + 4];
            }
#pragma unroll
            for (int nt = 0; nt < 8; nt++) {
                uint4 b = ldfrag(Winitp, nh * 32 + wn * 8 + nt, kb, 16, lane);
                mma8(acc[nt], a[0], b.x, b.y);
                mma8(acc[nt], a[1], b.z, b.w);
            }
        }
#pragma unroll
        for (int nt = 0; nt < 8; nt++)
#pragma unroll
            for (int rix = 0; rix < 4; rix++) {
                int row = wm * 16 + g + 8 * (rix >> 1);
                int col = wn * 64 + nt * 8 + t4 * 2 + (rix & 1);
                initout[(rowBase + row) * 512 + nh * 256 + col] =
                    acc[nt][rix] + binit[nh * 256 + col];
            }
    }
}

// ---------------- GRU cell 1: fp16, full-tile staged, barrier-free mainloop ----------------
// dyn smem: Xs[64*132] | Hs[64*132] half2 words (stride 132 -> conflict-free)
__global__ __launch_bounds__(256, 2) void k_gru1_mma(
    const float* __restrict__ x_in, const float* __restrict__ h_in,
    const uint32_t* __restrict__ Wihh, const uint32_t* __restrict__ Whhh,
    const float* __restrict__ bih, const float* __restrict__ bhh,
    float* __restrict__ h_out)
{
    extern __shared__ __align__(16) uint32_t SM1[];
    uint32_t* Xs = SM1;             // 64*132
    uint32_t* Hs = SM1 + 64 * 132;  // 64*132

    const int tid = threadIdx.x;
    const int m0 = blockIdx.y * 64, c0b = blockIdx.x * 64;
    const int warp = tid >> 5, lane = tid & 31;
    const int wm = warp >> 2, wn = warp & 3;
    const int g = lane >> 2, t4 = lane & 3;
    const int lr = tid >> 2, lq = tid & 3;

    float accR[2][2][4], accZ[2][2][4], accIN[2][2][4], accHN[2][2][4];
#pragma unroll
    for (int mf = 0; mf < 2; mf++)
#pragma unroll
        for (int nt = 0; nt < 2; nt++)
#pragma unroll
            for (int j = 0; j < 4; j++) {
                accR[mf][nt][j] = 0.0f; accZ[mf][nt][j] = 0.0f;
                accIN[mf][nt][j] = 0.0f; accHN[mf][nt][j] = 0.0f;
            }

    // stage ALL of X and H (fp16), one barrier
#pragma unroll
    for (int c = 0; c < 16; c++) {
        int col = c * 16 + lq * 4;
        float4 xv = *(const float4*)&x_in[(m0 + lr) * 256 + col];
        float4 hv = *(const float4*)&h_in[(m0 + lr) * 256 + col];
        int w = lr * 132 + c * 8 + lq * 2;
        Xs[w]     = f2h2(xv.x, xv.y);
        Xs[w + 1] = f2h2(xv.z, xv.w);
        Hs[w]     = f2h2(hv.x, hv.y);
        Hs[w + 1] = f2h2(hv.z, hv.w);
    }
    __syncthreads();

    // barrier-free mainloop over 16 k16 tiles
    for (int kt = 0; kt < 16; kt++) {
        uint32_t ax[2][4], ah[2][4];
#pragma unroll
        for (int mf = 0; mf < 2; mf++) {
            int rb = wm * 32 + mf * 16 + g;
            int w0 = rb * 132 + kt * 8 + t4;
            int w1 = (rb + 8) * 132 + kt * 8 + t4;
            ax[mf][0] = Xs[w0];
            ax[mf][1] = Xs[w1];
            ax[mf][2] = Xs[w0 + 4];
            ax[mf][3] = Xs[w1 + 4];
            ah[mf][0] = Hs[w0];
            ah[mf][1] = Hs[w1];
            ah[mf][2] = Hs[w0 + 4];
            ah[mf][3] = Hs[w1 + 4];
        }

#pragma unroll
        for (int nt = 0; nt < 2; nt++) {
            int nbB = (c0b + wn * 16 + nt * 8) >> 3;
            uint2 b_ir = ldfragh(Wihh,      nbB, kt, lane);
            uint2 b_iz = ldfragh(Wihh, 32 + nbB, kt, lane);
            uint2 b_in = ldfragh(Wihh, 64 + nbB, kt, lane);
            uint2 b_hr = ldfragh(Whhh,      nbB, kt, lane);
            uint2 b_hz = ldfragh(Whhh, 32 + nbB, kt, lane);
            uint2 b_hn = ldfragh(Whhh, 64 + nbB, kt, lane);
#pragma unroll
            for (int mf = 0; mf < 2; mf++) {
                mma16(accR[mf][nt],  ax[mf], b_ir.x, b_ir.y);
                mma16(accR[mf][nt],  ah[mf], b_hr.x, b_hr.y);
                mma16(accZ[mf][nt],  ax[mf], b_iz.x, b_iz.y);
                mma16(accZ[mf][nt],  ah[mf], b_hz.x, b_hz.y);
                mma16(accIN[mf][nt], ax[mf], b_in.x, b_in.y);
                mma16(accHN[mf][nt], ah[mf], b_hn.x, b_hn.y);
            }
        }
    }

#pragma unroll
    for (int mf = 0; mf < 2; mf++)
#pragma unroll
        for (int nt = 0; nt < 2; nt++)
#pragma unroll
            for (int rix = 0; rix < 4; rix++) {
                int row = m0 + wm * 32 + mf * 16 + g + 8 * (rix >> 1);
                int col = c0b + wn * 16 + nt * 8 + t4 * 2 + (rix & 1);
                float r = sigm(accR[mf][nt][rix] + bih[col] + bhh[col]);
                float z = sigm(accZ[mf][nt][rix] + bih[col + 256] + bhh[col + 256]);
                float n = tanhf(accIN[mf][nt][rix] + bih[col + 512] +
                                r * (accHN[mf][nt][rix] + bhh[col + 512]));
                float hold = h_in[row * 256 + col];
                h_out[row * 256 + col] = (1.0f - z) * n + z * hold;
            }
}

// ---------------- GRU cell 0: tf32 x-path + fp16 h-path, staged-once, barrier-free ----------------
__global__ __launch_bounds__(256, 2) void k_gru0_mma(
    const float* __restrict__ a_in, const float* __restrict__ h_in,
    const uint32_t* __restrict__ Wih0p, const uint32_t* __restrict__ Whhh,
    const float* __restrict__ bih, const float* __restrict__ bhh,
    float* __restrict__ h_out)
{
    extern __shared__ __align__(16) uint32_t SM0[];
    uint32_t* Hs = SM0;             // 64*132
    uint32_t* As = SM0 + 64 * 132;  // 64*12 (tf32)

    const int tid = threadIdx.x;
    const int m0 = blockIdx.y * 64, c0b = blockIdx.x * 64;
    const int warp = tid >> 5, lane = tid & 31;
    const int wm = warp >> 2, wn = warp & 3;
    const int g = lane >> 2, t4 = lane & 3;
    const int lr = tid >> 2, lq = tid & 3;

    float accR[2][2][4], accZ[2][2][4], accIN[2][2][4], accHN[2][2][4];
#pragma unroll
    for (int mf = 0; mf < 2; mf++)
#pragma unroll
        for (int nt = 0; nt < 2; nt++)
#pragma unroll
            for (int j = 0; j < 4; j++) {
                accR[mf][nt][j] = 0.0f; accZ[mf][nt][j] = 0.0f;
                accIN[mf][nt][j] = 0.0f; accHN[mf][nt][j] = 0.0f;
            }

    // stage a-tile (tf32) and ALL of H (fp16), one barrier
    {
        int k2 = lq * 2;
        float2 av = *(const float2*)&a_in[(m0 + lr) * 8 + k2];
        As[lr * 12 + k2] = f2tf(av.x); As[lr * 12 + k2 + 1] = f2tf(av.y);
    }
#pragma unroll
    for (int c = 0; c < 16; c++) {
        int col = c * 16 + lq * 4;
        float4 hv = *(const float4*)&h_in[(m0 + lr) * 256 + col];
        int w = lr * 132 + c * 8 + lq * 2;
        Hs[w]     = f2h2(hv.x, hv.y);
        Hs[w + 1] = f2h2(hv.z, hv.w);
    }
    __syncthreads();

    // x path (K=8, tf32)
    {
        uint32_t a[2][4];
#pragma unroll
        for (int mf = 0; mf < 2; mf++) {
            int rb = wm * 32 + mf * 16 + g;
            a[mf][0] = As[rb * 12 + t4];
            a[mf][1] = As[(rb + 8) * 12 + t4];
            a[mf][2] = As[rb * 12 + t4 + 4];
            a[mf][3] = As[(rb + 8) * 12 + t4 + 4];
        }
#pragma unroll
        for (int nt = 0; nt < 2; nt++) {
            int nbB = (c0b + wn * 16 + nt * 8) >> 3;
            uint2 b_ir = *(const uint2*)&Wih0p[((     nbB) * 32 + lane) * 2];
            uint2 b_iz = *(const uint2*)&Wih0p[((32 + nbB) * 32 + lane) * 2];
            uint2 b_in = *(const uint2*)&Wih0p[((64 + nbB) * 32 + lane) * 2];
#pragma unroll
            for (int mf = 0; mf < 2; mf++) {
                mma8(accR[mf][nt],  a[mf], b_ir.x, b_ir.y);
                mma8(accZ[mf][nt],  a[mf], b_iz.x, b_iz.y);
                mma8(accIN[mf][nt], a[mf], b_in.x, b_in.y);
            }
        }
    }

    // h path: barrier-free
    for (int kt = 0; kt < 16; kt++) {
        uint32_t ah[2][4];
#pragma unroll
        for (int mf = 0; mf < 2; mf++) {
            int rb = wm * 32 + mf * 16 + g;
            int w0 = rb * 132 + kt * 8 + t4;
            int w1 = (rb + 8) * 132 + kt * 8 + t4;
            ah[mf][0] = Hs[w0];
            ah[mf][1] = Hs[w1];
            ah[mf][2] = Hs[w0 + 4];
            ah[mf][3] = Hs[w1 + 4];
        }

#pragma unroll
        for (int nt = 0; nt < 2; nt++) {
            int nbB = (c0b + wn * 16 + nt * 8) >> 3;
            uint2 b_hr = ldfragh(Whhh,      nbB, kt, lane);
            uint2 b_hz = ldfragh(Whhh, 32 + nbB, kt, lane);
            uint2 b_hn = ldfragh(Whhh, 64 + nbB, kt, lane);
#pragma unroll
            for (int mf = 0; mf < 2; mf++) {
                mma16(accR[mf][nt],  ah[mf], b_hr.x, b_hr.y);
                mma16(accZ[mf][nt],  ah[mf], b_hz.x, b_hz.y);
                mma16(accHN[mf][nt], ah[mf], b_hn.x, b_hn.y);
            }
        }
    }

#pragma unroll
    for (int mf = 0; mf < 2; mf++)
#pragma unroll
        for (int nt = 0; nt < 2; nt++)
#pragma unroll
            for (int rix = 0; rix < 4; rix++) {
                int row = m0 + wm * 32 + mf * 16 + g + 8 * (rix >> 1);
                int col = c0b + wn * 16 + nt * 8 + t4 * 2 + (rix & 1);
                float r = sigm(accR[mf][nt][rix] + bih[col] + bhh[col]);
                float z = sigm(accZ[mf][nt][rix] + bih[col + 256] + bhh[col + 256]);
                float n = tanhf(accIN[mf][nt][rix] + bih[col + 512] +
                                r * (accHN[mf][nt][rix] + bhh[col + 512]));
                float hold = h_in[row * 256 + col];
                h_out[row * 256 + col] = (1.0f - z) * n + z * hold;
            }
}

// ---------------- logits + softmax ----------------
__global__ __launch_bounds__(256) void k_logits(
    const float* __restrict__ h, const float* __restrict__ Wa,
    const float* __restrict__ ba, float* __restrict__ out,
    float* __restrict__ a_next, int t)
{
    __shared__ float hs[32][257];
    __shared__ float Was[8][257];

    const int tid = threadIdx.x;
    const int rb0 = blockIdx.x * 32;

#pragma unroll
    for (int i = 0; i < 8; i++) {
        int idx = i * 256 + tid;
        int j = idx >> 8, k = idx & 255;
        Was[j][k] = Wa[j * 256 + k];
    }
#pragma unroll
    for (int i = 0; i < 32; i++) {
        int idx = i * 256 + tid;
        int r = idx >> 8, k = idx & 255;
        hs[r][k] = h[(rb0 + r) * 256 + k];
    }
    __syncthreads();

    const int r = tid >> 3, j = tid & 7;
    float s0 = 0.0f, s1 = 0.0f, s2 = 0.0f, s3 = 0.0f;
#pragma unroll 8
    for (int k = 0; k < 256; k += 4) {
        s0 += hs[r][k + 0] * Was[j][k + 0];
        s1 += hs[r][k + 1] * Was[j][k + 1];
        s2 += hs[r][k + 2] * Was[j][k + 2];
        s3 += hs[r][k + 3] * Was[j][k + 3];
    }
    float acc = (s0 + s1) + (s2 + s3) + ba[j];

    out[(rb0 + r) * (HOR * ACT) + t * ACT + j] = acc;

    float m = acc;
#pragma unroll
    for (int o = 4; o; o >>= 1) m = fmaxf(m, __shfl_xor_sync(0xffffffffu, m, o));
    float e = expf(acc - m);
    float s = e;
#pragma unroll
    for (int o = 4; o; o >>= 1) s += __shfl_xor_sync(0xffffffffu, s, o);
    a_next[(rb0 + r) * ACT + j] = e / s;
}

// ---------------- host ----------------
extern "C" void kernel_launch(void* const* d_in, const int* in_sizes, int n_in,
                              void* d_out, int out_size)
{
    const float* s0    = (const float*)d_in[0];
    const float* s1    = (const float*)d_in[1];
    const float* W1    = (const float*)d_in[3];
    const float* b1    = (const float*)d_in[4];
    const float* lng   = (const float*)d_in[5];
    const float* lnb   = (const float*)d_in[6];
    const float* W2    = (const float*)d_in[7];
    const float* b2    = (const float*)d_in[8];
    const float* Wih0  = (const float*)d_in[9];
    const float* Whh0  = (const float*)d_in[10];
    const float* bih0  = (const float*)d_in[11];
    const float* bhh0  = (const float*)d_in[12];
    const float* Wih1  = (const float*)d_in[13];
    const float* Whh1  = (const float*)d_in[14];
    const float* bih1  = (const float*)d_in[15];
    const float* bhh1  = (const float*)d_in[16];
    const float* Wa    = (const float*)d_in[17];
    const float* ba    = (const float*)d_in[18];
    const float* Winit = (const float*)d_in[19];
    const float* binit = (const float*)d_in[20];
    float* out = (float*)d_out;

    float *initbuf, *h0b, *h1b, *a0, *a1;
    uint32_t *W1p, *W2p, *Winitp, *Wih1h, *Whh1h, *Whh0h, *Wih0p;
    cudaGetSymbolAddress((void**)&initbuf, g_init);
    cudaGetSymbolAddress((void**)&h0b, g_h0b);
    cudaGetSymbolAddress((void**)&h1b, g_h1b);
    cudaGetSymbolAddress((void**)&a0, g_a0);
    cudaGetSymbolAddress((void**)&a1, g_a1);
    cudaGetSymbolAddress((void**)&W1p, g_W1p);
    cudaGetSymbolAddress((void**)&W2p, g_W2p);
    cudaGetSymbolAddress((void**)&Winitp, g_Winitp);
    cudaGetSymbolAddress((void**)&Wih1h, g_Wih1h);
    cudaGetSymbolAddress((void**)&Whh1h, g_Whh1h);
    cudaGetSymbolAddress((void**)&Whh0h, g_Whh0h);
    cudaGetSymbolAddress((void**)&Wih0p, g_Wih0p);

    static int attrs_set = 0;
    const int MLP_SMEM = (8448 + 8320) * 4;
    const int G1_SMEM  = 2 * 64 * 132 * 4;            // 67584 B
    const int G0_SMEM  = (64 * 132 + 64 * 12) * 4;    // 36864 B
    if (!attrs_set) {
        cudaFuncSetAttribute(k_mlp, cudaFuncAttributeMaxDynamicSharedMemorySize, MLP_SMEM);
        cudaFuncSetAttribute(k_gru1_mma, cudaFuncAttributeMaxDynamicSharedMemorySize, G1_SMEM);
        cudaFuncSetAttribute(k_gru0_mma, cudaFuncAttributeMaxDynamicSharedMemorySize, G0_SMEM);
        attrs_set = 1;
    }

    // launch 1: fused pack + a0 zero
    k_pack_all<<<(PK_TOT + 255) / 256, 256>>>(W1, W2, Winit, Wih1, Whh1, Whh0, Wih0, a0);

    // launch 2: fused prologue MLP
    k_mlp<<<BATCH / 32, 256, MLP_SMEM>>>(s0, s1, W1p, b1, lng, lnb,
                                         W2p, b2, Winitp, binit, initbuf);

    float* h0bufs[2] = {initbuf, h0b};
    float* h1bufs[2] = {initbuf + BATCH * HID, h1b};
    float* abufs[2]  = {a0, a1};

    // launch 3: gru0(t=0); launch 4: gru1(t=0)  <- profiled slot
    for (int t = 0; t < HOR; t++) {
        int cur = t & 1, nxt = 1 - cur;
        k_gru0_mma<<<dim3(4, BATCH / 64), 256, G0_SMEM>>>(abufs[cur], h0bufs[cur],
                                                          Wih0p, Whh0h, bih0, bhh0, h0bufs[nxt]);
        k_gru1_mma<<<dim3(4, BATCH / 64), 256, G1_SMEM>>>(h0bufs[nxt], h1bufs[cur],
                                                          Wih1h, Whh1h, bih1, bhh1, h1bufs[nxt]);
        k_logits<<<BATCH / 32, 256>>>(h1bufs[nxt], Wa, ba, out, abufs[nxt], t);
    }
}